// round 4
// baseline (speedup 1.0000x reference)
#include <cuda_runtime.h>
#include <math.h>

#define BB 8
#define SS 1000
#define EE 1024
#define HH 16
#define DD 64
#define MM (BB*SS)        // 8000
#define STILES 16         // ceil(1000/64)

// Scratch (allocation-free rule: __device__ globals)
__device__ float g_q[BB*HH*SS*DD];
__device__ float g_k[BB*HH*SS*DD];
__device__ float g_v[BB*HH*SS*DD];
__device__ float g_y[BB*SS*EE];

// ---------------------------------------------------------------------------
// Kernel 1: QKV projection. C[m, h*64+d] = x[m,:] @ w[h,:,d] + b[h,d]
// Output layout: [B,H,S,D]. grid = (16 heads, 125 mtiles, 3 which)
// ---------------------------------------------------------------------------
__global__ __launch_bounds__(256) void qkv_gemm_kernel(
    const float* __restrict__ x,
    const float* __restrict__ wq, const float* __restrict__ bq,
    const float* __restrict__ wk, const float* __restrict__ bk,
    const float* __restrict__ wv, const float* __restrict__ bv)
{
    const int which = blockIdx.z;
    const float* w    = (which == 0) ? wq : (which == 1) ? wk : wv;
    const float* bias = (which == 0) ? bq : (which == 1) ? bk : bv;
    float* out        = (which == 0) ? g_q : (which == 1) ? g_k : g_v;

    __shared__ float As[16][65];   // [k][m]
    __shared__ float Bs[16][64];   // [k][n]

    const int tid = threadIdx.x;
    const int tx = tid & 15, ty = tid >> 4;
    const int m0 = blockIdx.y * 64;
    const int h  = blockIdx.x;

    const float* wh = w + h * EE * DD;
    float acc[4][4] = {};

    for (int k0 = 0; k0 < EE; k0 += 16) {
        // A: 64 rows x 16 k  (float4 global, scalar transposed smem stores)
        {
            int row = tid >> 2;
            int kk4 = (tid & 3) * 4;
            float4 a4 = *(const float4*)&x[(m0 + row) * EE + k0 + kk4];
            As[kk4 + 0][row] = a4.x;
            As[kk4 + 1][row] = a4.y;
            As[kk4 + 2][row] = a4.z;
            As[kk4 + 3][row] = a4.w;
        }
        // B: 16 k x 64 n (one head, contiguous)
        {
            int kk = tid >> 4;
            int n4 = (tid & 15) * 4;
            *(float4*)&Bs[kk][n4] = *(const float4*)&wh[(k0 + kk) * DD + n4];
        }
        __syncthreads();
        #pragma unroll
        for (int kk = 0; kk < 16; kk++) {
            float a[4];
            #pragma unroll
            for (int i = 0; i < 4; i++) a[i] = As[kk][ty * 4 + i];
            float4 b4 = *(float4*)&Bs[kk][tx * 4];
            float b[4] = {b4.x, b4.y, b4.z, b4.w};
            #pragma unroll
            for (int i = 0; i < 4; i++)
                #pragma unroll
                for (int j = 0; j < 4; j++)
                    acc[i][j] = fmaf(a[i], b[j], acc[i][j]);
        }
        __syncthreads();
    }

    const int d0 = tx * 4;
    float4 bi = *(const float4*)&bias[h * DD + d0];
    #pragma unroll
    for (int i = 0; i < 4; i++) {
        int m = m0 + ty * 4 + i;
        int b = m / SS, s = m % SS;
        float4 r;
        r.x = acc[i][0] + bi.x;
        r.y = acc[i][1] + bi.y;
        r.z = acc[i][2] + bi.z;
        r.w = acc[i][3] + bi.w;
        *(float4*)&out[((b * HH + h) * SS + s) * DD + d0] = r;
    }
}

// ---------------------------------------------------------------------------
// Kernel 2: causal flash attention, fp32, scale = 1/sqrt(S).
// grid = (16 qtiles, 128 bh); block = 256. Writes concat-head y[B,S,E].
// ---------------------------------------------------------------------------
__global__ __launch_bounds__(256) void flash_kernel()
{
    extern __shared__ float sm[];
    float* qs = sm;                 // 64 x 65
    float* ks = sm + 64 * 65;       // 64 x 65
    float* vs = sm + 2 * 64 * 65;   // 64 x 65
    float* ps = sm + 3 * 64 * 65;   // 64 x 65

    const int qt = blockIdx.x;
    const int bh = blockIdx.y;
    const int b  = bh >> 4;
    const int h  = bh & 15;

    const float* qb = g_q + (size_t)bh * SS * DD;
    const float* kb = g_k + (size_t)bh * SS * DD;
    const float* vb = g_v + (size_t)bh * SS * DD;

    const int tid = threadIdx.x;
    const int tx = tid & 15, ty = tid >> 4;
    const float scale = 0.031622776601683794f;  // 1/sqrt(1000)
    const float NEG_INF = __int_as_float(0xff800000);

    // load Q tile
    {
        int row = tid >> 4;           // 0..15
        int d4  = (tid & 15) * 4;
        #pragma unroll
        for (int r0 = 0; r0 < 64; r0 += 16) {
            int rr = r0 + row;
            int gs = qt * 64 + rr;
            float4 f = (gs < SS) ? *(const float4*)&qb[gs * DD + d4]
                                 : make_float4(0.f, 0.f, 0.f, 0.f);
            qs[rr * 65 + d4 + 0] = f.x;
            qs[rr * 65 + d4 + 1] = f.y;
            qs[rr * 65 + d4 + 2] = f.z;
            qs[rr * 65 + d4 + 3] = f.w;
        }
    }

    float o[4][4] = {};
    float mrow[4], lrow[4];
    #pragma unroll
    for (int i = 0; i < 4; i++) { mrow[i] = NEG_INF; lrow[i] = 0.f; }

    for (int jt = 0; jt <= qt; jt++) {
        __syncthreads();  // protect ks/vs/ps reuse (also covers q store on iter 0)
        // load K,V tiles
        {
            int row = tid >> 4;
            int d4  = (tid & 15) * 4;
            #pragma unroll
            for (int r0 = 0; r0 < 64; r0 += 16) {
                int rr = r0 + row;
                int gs = jt * 64 + rr;
                float4 fk, fv;
                if (gs < SS) {
                    fk = *(const float4*)&kb[gs * DD + d4];
                    fv = *(const float4*)&vb[gs * DD + d4];
                } else {
                    fk = make_float4(0.f, 0.f, 0.f, 0.f);
                    fv = fk;
                }
                ks[rr * 65 + d4 + 0] = fk.x; ks[rr * 65 + d4 + 1] = fk.y;
                ks[rr * 65 + d4 + 2] = fk.z; ks[rr * 65 + d4 + 3] = fk.w;
                vs[rr * 65 + d4 + 0] = fv.x; vs[rr * 65 + d4 + 1] = fv.y;
                vs[rr * 65 + d4 + 2] = fv.z; vs[rr * 65 + d4 + 3] = fv.w;
            }
        }
        __syncthreads();

        // scores: s[i][j] = q(row) . k(col)
        float s[4][4] = {};
        #pragma unroll 8
        for (int d = 0; d < 64; d++) {
            float a[4], bq_[4];
            #pragma unroll
            for (int i = 0; i < 4; i++) a[i]   = qs[(ty * 4 + i) * 65 + d];
            #pragma unroll
            for (int j = 0; j < 4; j++) bq_[j] = ks[(tx * 4 + j) * 65 + d];
            #pragma unroll
            for (int i = 0; i < 4; i++)
                #pragma unroll
                for (int j = 0; j < 4; j++)
                    s[i][j] = fmaf(a[i], bq_[j], s[i][j]);
        }

        // scale + (diagonal tile only) causal / length mask
        if (jt == qt) {
            #pragma unroll
            for (int i = 0; i < 4; i++) {
                int grow = qt * 64 + ty * 4 + i;
                #pragma unroll
                for (int j = 0; j < 4; j++) {
                    int gcol = jt * 64 + tx * 4 + j;
                    s[i][j] = (gcol > grow || gcol >= SS) ? NEG_INF : s[i][j] * scale;
                }
            }
        } else {
            #pragma unroll
            for (int i = 0; i < 4; i++)
                #pragma unroll
                for (int j = 0; j < 4; j++)
                    s[i][j] *= scale;
        }

        // online softmax
        #pragma unroll
        for (int i = 0; i < 4; i++) {
            float rm = s[i][0];
            #pragma unroll
            for (int j = 1; j < 4; j++) rm = fmaxf(rm, s[i][j]);
            #pragma unroll
            for (int off = 8; off >= 1; off >>= 1)
                rm = fmaxf(rm, __shfl_xor_sync(0xffffffffu, rm, off, 16));
            float mnew = fmaxf(mrow[i], rm);
            float alpha = __expf(mrow[i] - mnew);
            float rs = 0.f;
            #pragma unroll
            for (int j = 0; j < 4; j++) {
                s[i][j] = __expf(s[i][j] - mnew);   // p
                rs += s[i][j];
            }
            #pragma unroll
            for (int off = 8; off >= 1; off >>= 1)
                rs += __shfl_xor_sync(0xffffffffu, rs, off, 16);
            lrow[i] = lrow[i] * alpha + rs;
            mrow[i] = mnew;
            #pragma unroll
            for (int j = 0; j < 4; j++) o[i][j] *= alpha;
            // stash p into smem
            #pragma unroll
            for (int j = 0; j < 4; j++)
                ps[(ty * 4 + i) * 65 + tx * 4 + j] = s[i][j];
        }
        __syncthreads();

        // o += p @ v
        #pragma unroll 8
        for (int kk = 0; kk < 64; kk++) {
            float pv[4], vv[4];
            #pragma unroll
            for (int i = 0; i < 4; i++) pv[i] = ps[(ty * 4 + i) * 65 + kk];
            #pragma unroll
            for (int j = 0; j < 4; j++) vv[j] = vs[kk * 65 + tx * 4 + j];
            #pragma unroll
            for (int i = 0; i < 4; i++)
                #pragma unroll
                for (int j = 0; j < 4; j++)
                    o[i][j] = fmaf(pv[i], vv[j], o[i][j]);
        }
    }

    // write: y[b, s, h*64+d]
    #pragma unroll
    for (int i = 0; i < 4; i++) {
        int grow = qt * 64 + ty * 4 + i;
        if (grow < SS) {
            float inv = 1.f / lrow[i];
            float4 r;
            r.x = o[i][0] * inv; r.y = o[i][1] * inv;
            r.z = o[i][2] * inv; r.w = o[i][3] * inv;
            *(float4*)&g_y[((size_t)b * SS + grow) * EE + h * DD + tx * 4] = r;
        }
    }
}

// ---------------------------------------------------------------------------
// Kernel 3: out = GELU(y @ wp + bp). grid = (16 ntiles, 125 mtiles)
// ---------------------------------------------------------------------------
__global__ __launch_bounds__(256) void proj_gelu_kernel(
    const float* __restrict__ wp, const float* __restrict__ bp,
    float* __restrict__ out)
{
    __shared__ float As[16][65];
    __shared__ float Bs[16][64];

    const int tid = threadIdx.x;
    const int tx = tid & 15, ty = tid >> 4;
    const int m0 = blockIdx.y * 64;
    const int n0 = blockIdx.x * 64;

    float acc[4][4] = {};

    for (int k0 = 0; k0 < EE; k0 += 16) {
        {
            int row = tid >> 2;
            int kk4 = (tid & 3) * 4;
            float4 a4 = *(const float4*)&g_y[(size_t)(m0 + row) * EE + k0 + kk4];
            As[kk4 + 0][row] = a4.x;
            As[kk4 + 1][row] = a4.y;
            As[kk4 + 2][row] = a4.z;
            As[kk4 + 3][row] = a4.w;
        }
        {
            int kk = tid >> 4;
            int n4 = (tid & 15) * 4;
            *(float4*)&Bs[kk][n4] = *(const float4*)&wp[(size_t)(k0 + kk) * EE + n0 + n4];
        }
        __syncthreads();
        #pragma unroll
        for (int kk = 0; kk < 16; kk++) {
            float a[4];
            #pragma unroll
            for (int i = 0; i < 4; i++) a[i] = As[kk][ty * 4 + i];
            float4 b4 = *(float4*)&Bs[kk][tx * 4];
            float b[4] = {b4.x, b4.y, b4.z, b4.w};
            #pragma unroll
            for (int i = 0; i < 4; i++)
                #pragma unroll
                for (int j = 0; j < 4; j++)
                    acc[i][j] = fmaf(a[i], b[j], acc[i][j]);
        }
        __syncthreads();
    }

    float4 bi = *(const float4*)&bp[n0 + tx * 4];
    float bb[4] = {bi.x, bi.y, bi.z, bi.w};
    #pragma unroll
    for (int i = 0; i < 4; i++) {
        int m = m0 + ty * 4 + i;
        float4 r;
        float* rp = &r.x;
        #pragma unroll
        for (int j = 0; j < 4; j++) {
            float t = acc[i][j] + bb[j];
            rp[j] = 0.5f * t * (1.0f + erff(t * 0.70710678118654752f));
        }
        *(float4*)&out[(size_t)m * EE + n0 + tx * 4] = r;
    }
}

// ---------------------------------------------------------------------------
extern "C" void kernel_launch(void* const* d_in, const int* in_sizes, int n_in,
                              void* d_out, int out_size)
{
    const float* x  = (const float*)d_in[0];
    const float* wq = (const float*)d_in[1];
    const float* bq = (const float*)d_in[2];
    const float* wk = (const float*)d_in[3];
    const float* bk = (const float*)d_in[4];
    const float* wv = (const float*)d_in[5];
    const float* bv = (const float*)d_in[6];
    const float* wp = (const float*)d_in[7];
    const float* bp = (const float*)d_in[8];
    float* out = (float*)d_out;

    // QKV projections
    dim3 g1(HH, MM / 64, 3);
    qkv_gemm_kernel<<<g1, 256>>>(x, wq, bq, wk, bk, wv, bv);

    // Flash attention
    const int smem = 4 * 64 * 65 * sizeof(float);  // 66560 B
    cudaFuncSetAttribute(flash_kernel, cudaFuncAttributeMaxDynamicSharedMemorySize, smem);
    dim3 g2(STILES, BB * HH);
    flash_kernel<<<g2, 256, smem>>>();

    // Output projection + GELU
    dim3 g3(EE / 64, MM / 64);
    proj_gelu_kernel<<<g3, 256>>>(wp, bp, out);
}

// round 5
// speedup vs baseline: 1.4982x; 1.4982x over previous
#include <cuda_runtime.h>
#include <math.h>

#define BB 8
#define SS 1000
#define EE 1024
#define HH 16
#define DD 64
#define MM (BB*SS)        // 8000
#define STILES 16         // ceil(1000/64)

#define Bb_M 128
#define Bb_N 64
#define Bb_K 16
#define NIT (EE/Bb_K)     // 64
#define MTILES ((MM + Bb_M - 1)/Bb_M)   // 63

// Scratch (allocation-free rule: __device__ globals)
__device__ float g_q[BB*HH*SS*DD];
__device__ float g_k[BB*HH*SS*DD];
__device__ float g_v[BB*HH*SS*DD];
__device__ float g_y[BB*SS*EE];

// ---------------------------------------------------------------------------
// TF32 helpers
// ---------------------------------------------------------------------------
__device__ __forceinline__ unsigned f2tf(float f) {
    unsigned u;
    asm("cvt.rna.tf32.f32 %0, %1;" : "=r"(u) : "f"(f));
    return u;
}

__device__ __forceinline__ void mma8(float* d, const unsigned* a, const unsigned* b) {
    asm volatile(
        "mma.sync.aligned.m16n8k8.row.col.f32.tf32.tf32.f32 "
        "{%0,%1,%2,%3}, {%4,%5,%6,%7}, {%8,%9}, {%0,%1,%2,%3};"
        : "+f"(d[0]), "+f"(d[1]), "+f"(d[2]), "+f"(d[3])
        : "r"(a[0]), "r"(a[1]), "r"(a[2]), "r"(a[3]),
          "r"(b[0]), "r"(b[1]));
}

// ---------------------------------------------------------------------------
// Shared 128x64 TF32 GEMM core.
// A: row-major [MM, EE], rows m0..m0+127 (guarded).
// B: B[k*ldb + n], n in [0,64).
// smem layouts (uint = tf32 bits), permuted k within each 8-slab so that
// fragment pairs (k, k+4) are adjacent -> single LDS.64, conflict-free:
//   sA[buf][slab][row(128)][8],  sB[buf][slab][n(64)][8]
// Warp layout: 8 warps, wm = wid>>1 (4 x 32 rows), wn = wid&1 (2 x 32 cols).
// ---------------------------------------------------------------------------
struct Stage {
    float4 a0, a1;   // A row slab: k 0..3, 4..7
    float4 b;        // B: one k-row, 4 n
};

__device__ __forceinline__ void gemm_ldg(Stage& st, const float* __restrict__ Ag,
                                         int am, int aslab,
                                         const float* __restrict__ Bg, int ldb,
                                         int bk, int bn, int it)
{
    const int k0 = it * Bb_K;
    if (am < MM) {
        const float* ap = Ag + (size_t)am * EE + k0 + aslab * 8;
        st.a0 = *(const float4*)ap;
        st.a1 = *(const float4*)(ap + 4);
    } else {
        st.a0 = make_float4(0.f, 0.f, 0.f, 0.f);
        st.a1 = st.a0;
    }
    st.b = *(const float4*)&Bg[(size_t)(k0 + bk) * ldb + bn];
}

__device__ __forceinline__ void gemm_sts(const Stage& st, unsigned* sA, unsigned* sB,
                                         int buf, int arow, int aslab,
                                         int bk, int bn)
{
    unsigned* pa = sA + buf * 2048 + aslab * 1024 + arow * 8;
    pa[0] = f2tf(st.a0.x); pa[1] = f2tf(st.a1.x);
    pa[2] = f2tf(st.a0.y); pa[3] = f2tf(st.a1.y);
    pa[4] = f2tf(st.a0.z); pa[5] = f2tf(st.a1.z);
    pa[6] = f2tf(st.a0.w); pa[7] = f2tf(st.a1.w);

    const int bslab = bk >> 3;
    const int bkp   = 2 * (bk & 3) + ((bk >> 2) & 1);
    unsigned* pb = sB + buf * 1024 + bslab * 512 + bn * 8 + bkp;
    pb[0]  = f2tf(st.b.x);
    pb[8]  = f2tf(st.b.y);
    pb[16] = f2tf(st.b.z);
    pb[24] = f2tf(st.b.w);
}

__device__ __forceinline__ void gemm_compute(const unsigned* sA, const unsigned* sB,
                                             int buf, int wm, int wn, int g, int t,
                                             float acc[2][4][4])
{
    #pragma unroll
    for (int s = 0; s < 2; s++) {
        const unsigned* Ab = sA + buf * 2048 + s * 1024;
        const unsigned* Bb = sB + buf * 1024 + s * 512;
        unsigned a[2][4], b[4][2];
        #pragma unroll
        for (int mt = 0; mt < 2; mt++) {
            int r = wm * 32 + mt * 16 + g;
            uint2 lo = *(const uint2*)(Ab + r * 8 + 2 * t);
            uint2 hi = *(const uint2*)(Ab + (r + 8) * 8 + 2 * t);
            a[mt][0] = lo.x; a[mt][2] = lo.y;
            a[mt][1] = hi.x; a[mt][3] = hi.y;
        }
        #pragma unroll
        for (int nt = 0; nt < 4; nt++) {
            int n = wn * 32 + nt * 8 + g;
            uint2 bb = *(const uint2*)(Bb + n * 8 + 2 * t);
            b[nt][0] = bb.x; b[nt][1] = bb.y;
        }
        #pragma unroll
        for (int mt = 0; mt < 2; mt++)
            #pragma unroll
            for (int nt = 0; nt < 4; nt++)
                mma8(acc[mt][nt], a[mt], b[nt]);
    }
}

__device__ __forceinline__ void gemm_main(const float* __restrict__ Ag, int m0,
                                          const float* __restrict__ Bg, int ldb,
                                          unsigned* sA, unsigned* sB,
                                          float acc[2][4][4])
{
    const int tid  = threadIdx.x;
    const int lane = tid & 31, wid = tid >> 5;
    const int g = lane >> 2, t = lane & 3;
    const int wm = wid >> 1, wn = wid & 1;

    const int arow  = tid >> 1;
    const int aslab = tid & 1;
    const int am    = m0 + arow;
    const int bk    = tid & 15;
    const int bn    = (tid >> 4) * 4;

    Stage st;
    gemm_ldg(st, Ag, am, aslab, Bg, ldb, bk, bn, 0);
    gemm_sts(st, sA, sB, 0, arow, aslab, bk, bn);
    __syncthreads();

    int buf = 0;
    for (int it = 0; it < NIT; it++) {
        if (it + 1 < NIT)
            gemm_ldg(st, Ag, am, aslab, Bg, ldb, bk, bn, it + 1);
        gemm_compute(sA, sB, buf, wm, wn, g, t, acc);
        if (it + 1 < NIT) {
            gemm_sts(st, sA, sB, buf ^ 1, arow, aslab, bk, bn);
            __syncthreads();
            buf ^= 1;
        }
    }
}

// ---------------------------------------------------------------------------
// Kernel 1: QKV projection (tensor core). grid = (16 heads, 63 mtiles, 3)
// out[((b*HH+h)*SS+s)*DD + d] = x[m,:] @ w[h,:,d] + bias[h,d]
// ---------------------------------------------------------------------------
__global__ __launch_bounds__(256) void qkv_gemm_kernel(
    const float* __restrict__ x,
    const float* __restrict__ wq, const float* __restrict__ bq,
    const float* __restrict__ wk, const float* __restrict__ bk_,
    const float* __restrict__ wv, const float* __restrict__ bv)
{
    __shared__ unsigned sA[2 * 2 * 128 * 8];
    __shared__ unsigned sB[2 * 2 * 64 * 8];

    const int which = blockIdx.z;
    const float* w    = (which == 0) ? wq : (which == 1) ? wk : wv;
    const float* bias = (which == 0) ? bq : (which == 1) ? bk_ : bv;
    float* out        = (which == 0) ? g_q : (which == 1) ? g_k : g_v;

    const int h  = blockIdx.x;
    const int m0 = blockIdx.y * Bb_M;

    float acc[2][4][4] = {};
    gemm_main(x, m0, w + (size_t)h * EE * DD, DD, sA, sB, acc);

    const int tid  = threadIdx.x;
    const int lane = tid & 31, wid = tid >> 5;
    const int g = lane >> 2, t = lane & 3;
    const int wm = wid >> 1, wn = wid & 1;

    #pragma unroll
    for (int nt = 0; nt < 4; nt++) {
        const int col = wn * 32 + nt * 8 + 2 * t;
        const float bi0 = bias[h * DD + col];
        const float bi1 = bias[h * DD + col + 1];
        #pragma unroll
        for (int mt = 0; mt < 2; mt++) {
            #pragma unroll
            for (int half = 0; half < 2; half++) {
                const int m = m0 + wm * 32 + mt * 16 + g + half * 8;
                if (m < MM) {
                    const int b = m / SS, s = m % SS;
                    float2 r;
                    r.x = acc[mt][nt][half * 2 + 0] + bi0;
                    r.y = acc[mt][nt][half * 2 + 1] + bi1;
                    *(float2*)&out[((size_t)(b * HH + h) * SS + s) * DD + col] = r;
                }
            }
        }
    }
}

// ---------------------------------------------------------------------------
// Kernel 2: causal flash attention, fp32, scale = 1/sqrt(S). (unchanged)
// grid = (16 qtiles, 128 bh); block = 256. Writes concat-head y[B,S,E].
// ---------------------------------------------------------------------------
__global__ __launch_bounds__(256) void flash_kernel()
{
    extern __shared__ float sm[];
    float* qs = sm;                 // 64 x 65
    float* ks = sm + 64 * 65;       // 64 x 65
    float* vs = sm + 2 * 64 * 65;   // 64 x 65
    float* ps = sm + 3 * 64 * 65;   // 64 x 65

    const int qt = blockIdx.x;
    const int bh = blockIdx.y;
    const int b  = bh >> 4;
    const int h  = bh & 15;

    const float* qb = g_q + (size_t)bh * SS * DD;
    const float* kb = g_k + (size_t)bh * SS * DD;
    const float* vb = g_v + (size_t)bh * SS * DD;

    const int tid = threadIdx.x;
    const int tx = tid & 15, ty = tid >> 4;
    const float scale = 0.031622776601683794f;  // 1/sqrt(1000)
    const float NEG_INF = __int_as_float(0xff800000);

    // load Q tile
    {
        int row = tid >> 4;           // 0..15
        int d4  = (tid & 15) * 4;
        #pragma unroll
        for (int r0 = 0; r0 < 64; r0 += 16) {
            int rr = r0 + row;
            int gs = qt * 64 + rr;
            float4 f = (gs < SS) ? *(const float4*)&qb[gs * DD + d4]
                                 : make_float4(0.f, 0.f, 0.f, 0.f);
            qs[rr * 65 + d4 + 0] = f.x;
            qs[rr * 65 + d4 + 1] = f.y;
            qs[rr * 65 + d4 + 2] = f.z;
            qs[rr * 65 + d4 + 3] = f.w;
        }
    }

    float o[4][4] = {};
    float mrow[4], lrow[4];
    #pragma unroll
    for (int i = 0; i < 4; i++) { mrow[i] = NEG_INF; lrow[i] = 0.f; }

    for (int jt = 0; jt <= qt; jt++) {
        __syncthreads();  // protect ks/vs/ps reuse (also covers q store on iter 0)
        // load K,V tiles
        {
            int row = tid >> 4;
            int d4  = (tid & 15) * 4;
            #pragma unroll
            for (int r0 = 0; r0 < 64; r0 += 16) {
                int rr = r0 + row;
                int gs = jt * 64 + rr;
                float4 fk, fv;
                if (gs < SS) {
                    fk = *(const float4*)&kb[gs * DD + d4];
                    fv = *(const float4*)&vb[gs * DD + d4];
                } else {
                    fk = make_float4(0.f, 0.f, 0.f, 0.f);
                    fv = fk;
                }
                ks[rr * 65 + d4 + 0] = fk.x; ks[rr * 65 + d4 + 1] = fk.y;
                ks[rr * 65 + d4 + 2] = fk.z; ks[rr * 65 + d4 + 3] = fk.w;
                vs[rr * 65 + d4 + 0] = fv.x; vs[rr * 65 + d4 + 1] = fv.y;
                vs[rr * 65 + d4 + 2] = fv.z; vs[rr * 65 + d4 + 3] = fv.w;
            }
        }
        __syncthreads();

        // scores: s[i][j] = q(row) . k(col)
        float s[4][4] = {};
        #pragma unroll 8
        for (int d = 0; d < 64; d++) {
            float a[4], bq_[4];
            #pragma unroll
            for (int i = 0; i < 4; i++) a[i]   = qs[(ty * 4 + i) * 65 + d];
            #pragma unroll
            for (int j = 0; j < 4; j++) bq_[j] = ks[(tx * 4 + j) * 65 + d];
            #pragma unroll
            for (int i = 0; i < 4; i++)
                #pragma unroll
                for (int j = 0; j < 4; j++)
                    s[i][j] = fmaf(a[i], bq_[j], s[i][j]);
        }

        // scale + (diagonal tile only) causal / length mask
        if (jt == qt) {
            #pragma unroll
            for (int i = 0; i < 4; i++) {
                int grow = qt * 64 + ty * 4 + i;
                #pragma unroll
                for (int j = 0; j < 4; j++) {
                    int gcol = jt * 64 + tx * 4 + j;
                    s[i][j] = (gcol > grow || gcol >= SS) ? NEG_INF : s[i][j] * scale;
                }
            }
        } else {
            #pragma unroll
            for (int i = 0; i < 4; i++)
                #pragma unroll
                for (int j = 0; j < 4; j++)
                    s[i][j] *= scale;
        }

        // online softmax
        #pragma unroll
        for (int i = 0; i < 4; i++) {
            float rm = s[i][0];
            #pragma unroll
            for (int j = 1; j < 4; j++) rm = fmaxf(rm, s[i][j]);
            #pragma unroll
            for (int off = 8; off >= 1; off >>= 1)
                rm = fmaxf(rm, __shfl_xor_sync(0xffffffffu, rm, off, 16));
            float mnew = fmaxf(mrow[i], rm);
            float alpha = __expf(mrow[i] - mnew);
            float rs = 0.f;
            #pragma unroll
            for (int j = 0; j < 4; j++) {
                s[i][j] = __expf(s[i][j] - mnew);   // p
                rs += s[i][j];
            }
            #pragma unroll
            for (int off = 8; off >= 1; off >>= 1)
                rs += __shfl_xor_sync(0xffffffffu, rs, off, 16);
            lrow[i] = lrow[i] * alpha + rs;
            mrow[i] = mnew;
            #pragma unroll
            for (int j = 0; j < 4; j++) o[i][j] *= alpha;
            // stash p into smem
            #pragma unroll
            for (int j = 0; j < 4; j++)
                ps[(ty * 4 + i) * 65 + tx * 4 + j] = s[i][j];
        }
        __syncthreads();

        // o += p @ v
        #pragma unroll 8
        for (int kk = 0; kk < 64; kk++) {
            float pv[4], vv[4];
            #pragma unroll
            for (int i = 0; i < 4; i++) pv[i] = ps[(ty * 4 + i) * 65 + kk];
            #pragma unroll
            for (int j = 0; j < 4; j++) vv[j] = vs[kk * 65 + tx * 4 + j];
            #pragma unroll
            for (int i = 0; i < 4; i++)
                #pragma unroll
                for (int j = 0; j < 4; j++)
                    o[i][j] = fmaf(pv[i], vv[j], o[i][j]);
        }
    }

    // write: y[b, s, h*64+d]
    #pragma unroll
    for (int i = 0; i < 4; i++) {
        int grow = qt * 64 + ty * 4 + i;
        if (grow < SS) {
            float inv = 1.f / lrow[i];
            float4 r;
            r.x = o[i][0] * inv; r.y = o[i][1] * inv;
            r.z = o[i][2] * inv; r.w = o[i][3] * inv;
            *(float4*)&g_y[((size_t)b * SS + grow) * EE + h * DD + tx * 4] = r;
        }
    }
}

// ---------------------------------------------------------------------------
// Kernel 3: out = GELU(y @ wp + bp), tensor core. grid = (16 ntiles, 63 mtiles)
// ---------------------------------------------------------------------------
__global__ __launch_bounds__(256) void proj_gelu_kernel(
    const float* __restrict__ wp, const float* __restrict__ bp,
    float* __restrict__ out)
{
    __shared__ unsigned sA[2 * 2 * 128 * 8];
    __shared__ unsigned sB[2 * 2 * 64 * 8];

    const int n0 = blockIdx.x * Bb_N;
    const int m0 = blockIdx.y * Bb_M;

    float acc[2][4][4] = {};
    gemm_main(g_y, m0, wp + n0, EE, sA, sB, acc);

    const int tid  = threadIdx.x;
    const int lane = tid & 31, wid = tid >> 5;
    const int g = lane >> 2, t = lane & 3;
    const int wm = wid >> 1, wn = wid & 1;

    #pragma unroll
    for (int nt = 0; nt < 4; nt++) {
        const int col = n0 + wn * 32 + nt * 8 + 2 * t;
        const float bi0 = bp[col];
        const float bi1 = bp[col + 1];
        #pragma unroll
        for (int mt = 0; mt < 2; mt++) {
            #pragma unroll
            for (int half = 0; half < 2; half++) {
                const int m = m0 + wm * 32 + mt * 16 + g + half * 8;
                if (m < MM) {
                    float t0 = acc[mt][nt][half * 2 + 0] + bi0;
                    float t1 = acc[mt][nt][half * 2 + 1] + bi1;
                    float2 r;
                    r.x = 0.5f * t0 * (1.0f + erff(t0 * 0.70710678118654752f));
                    r.y = 0.5f * t1 * (1.0f + erff(t1 * 0.70710678118654752f));
                    *(float2*)&out[(size_t)m * EE + col] = r;
                }
            }
        }
    }
}

// ---------------------------------------------------------------------------
extern "C" void kernel_launch(void* const* d_in, const int* in_sizes, int n_in,
                              void* d_out, int out_size)
{
    const float* x  = (const float*)d_in[0];
    const float* wq = (const float*)d_in[1];
    const float* bq = (const float*)d_in[2];
    const float* wk = (const float*)d_in[3];
    const float* bk = (const float*)d_in[4];
    const float* wv = (const float*)d_in[5];
    const float* bv = (const float*)d_in[6];
    const float* wp = (const float*)d_in[7];
    const float* bp = (const float*)d_in[8];
    float* out = (float*)d_out;

    // QKV projections (tensor core TF32)
    dim3 g1(HH, MTILES, 3);
    qkv_gemm_kernel<<<g1, 256>>>(x, wq, bq, wk, bk, wv, bv);

    // Flash attention (fp32 SIMT)
    const int smem = 4 * 64 * 65 * sizeof(float);  // 66560 B
    cudaFuncSetAttribute(flash_kernel, cudaFuncAttributeMaxDynamicSharedMemorySize, smem);
    dim3 g2(STILES, BB * HH);
    flash_kernel<<<g2, 256, smem>>>();

    // Output projection + GELU (tensor core TF32)
    dim3 g3(EE / Bb_N, MTILES);
    proj_gelu_kernel<<<g3, 256>>>(wp, bp, out);
}

// round 6
// speedup vs baseline: 1.5197x; 1.0144x over previous
#include <cuda_runtime.h>
#include <math.h>

#define BB 8
#define SS 1000
#define EE 1024
#define HH 16
#define DD 64
#define MM (BB*SS)        // 8000
#define STILES 16

#define TMm 128
#define TNn 128
#define TKk 16
#define NITER (EE/TKk)    // 64
#define MT ((MM + TMm - 1)/TMm)   // 63

// Scratch (allocation-free rule: __device__ globals)
__device__ float g_q[BB*HH*SS*DD];
__device__ float g_k[BB*HH*SS*DD];
__device__ float g_v[BB*HH*SS*DD];
__device__ float g_y[BB*SS*EE];

// ---------------------------------------------------------------------------
// TF32 helpers
// ---------------------------------------------------------------------------
__device__ __forceinline__ unsigned f2tf(float f) {
    unsigned u;
    asm("cvt.rna.tf32.f32 %0, %1;" : "=r"(u) : "f"(f));
    return u;
}

__device__ __forceinline__ void mma8(float* d, const unsigned* a, const unsigned* b) {
    asm volatile(
        "mma.sync.aligned.m16n8k8.row.col.f32.tf32.tf32.f32 "
        "{%0,%1,%2,%3}, {%4,%5,%6,%7}, {%8,%9}, {%0,%1,%2,%3};"
        : "+f"(d[0]), "+f"(d[1]), "+f"(d[2]), "+f"(d[3])
        : "r"(a[0]), "r"(a[1]), "r"(a[2]), "r"(a[3]),
          "r"(b[0]), "r"(b[1]));
}

// ---------------------------------------------------------------------------
// 128x128x16 TF32 GEMM core, 256 threads = 8 warps (2m x 4n), warp tile 64x32.
//
// sA layout (per buffer, 2048 words): word = row*16 + ((c ^ ((row>>1)&3))<<2) + j
//   where content at chunk c, slot j is k = 4*j + c  (k-permuted so one LDS.128
//   at chunk c=t yields k = {t, t+4, t+8, t+12}; XOR swizzle kills conflicts on
//   both the full-row STS.128 fill and the fragment LDS.128).
// sB layout (per buffer, 16*136 words): plain [k][n], row stride 136 (==8 mod 32
//   -> scalar fragment loads hit banks 8t+g: all 32 distinct; STS.128 fill
//   conflict-free by chunk arithmetic).
// ---------------------------------------------------------------------------
#define SA_WORDS 2048
#define SB_STRIDE 136
#define SB_WORDS (16*SB_STRIDE)   // 2176

struct BLQKV {
    const float* w;   // weight base for this 'which' (layout [H][E][D])
    int n0;           // column base within this which's 1024 cols
    __device__ __forceinline__ float4 ld(int k, int nq) const {
        int n = n0 + nq * 4;
        int h = n >> 6;
        int d = n & 63;
        return *(const float4*)&w[((size_t)h * EE + k) * DD + d];
    }
};

struct BLP {
    const float* wp;  // [E, E]
    int n0;
    __device__ __forceinline__ float4 ld(int k, int nq) const {
        return *(const float4*)&wp[(size_t)k * EE + n0 + nq * 4];
    }
};

template<class BL>
__device__ __forceinline__ void gemm_core(
    const float* __restrict__ Ag, int m0, const BL& bl,
    unsigned* sA, unsigned* sB, float acc[4][4][4])
{
    const int tid  = threadIdx.x;
    const int lane = tid & 31, wid = tid >> 5;
    const int g = lane >> 2, t = lane & 3;
    const int wm = wid >> 2, wn = wid & 3;

    // producer A: lanes 0-15 of each warp own full row wid*16+lane (16 k-floats)
    const int  arow = wid * 16 + lane;
    const bool doA  = lane < 16;
    const int  am   = m0 + arow;
    // producer B: every thread owns (k = tid>>4, n-quads tid&15 and (tid&15)+16)
    const int  bk  = tid >> 4;
    const int  bng = tid & 15;

    float fa[16];
    float4 fb0, fb1;

    const float* aptr = Ag + (size_t)am * EE;

    #define GEMM_LDG(it) do {                                               \
        const int k0_ = (it) * TKk;                                         \
        if (doA) {                                                          \
            if (am < MM) {                                                  \
                _Pragma("unroll")                                           \
                for (int q = 0; q < 4; q++) {                               \
                    float4 v = *(const float4*)&aptr[k0_ + q * 4];          \
                    fa[q*4+0] = v.x; fa[q*4+1] = v.y;                       \
                    fa[q*4+2] = v.z; fa[q*4+3] = v.w;                       \
                }                                                           \
            } else {                                                        \
                _Pragma("unroll")                                           \
                for (int i = 0; i < 16; i++) fa[i] = 0.f;                   \
            }                                                               \
        }                                                                   \
        fb0 = bl.ld(k0_ + bk, bng);                                         \
        fb1 = bl.ld(k0_ + bk, bng + 16);                                    \
    } while (0)

    #define GEMM_STS(buf) do {                                              \
        if (doA) {                                                          \
            unsigned* base_ = sA + (buf) * SA_WORDS + arow * 16;            \
            const int sw_ = (arow >> 1) & 3;                                \
            _Pragma("unroll")                                               \
            for (int c = 0; c < 4; c++) {                                   \
                uint4 u;                                                    \
                u.x = f2tf(fa[c]);     u.y = f2tf(fa[4 + c]);               \
                u.z = f2tf(fa[8 + c]); u.w = f2tf(fa[12 + c]);              \
                *(uint4*)(base_ + ((c ^ sw_) << 2)) = u;                    \
            }                                                               \
        }                                                                   \
        unsigned* bb_ = sB + (buf) * SB_WORDS + bk * SB_STRIDE;             \
        uint4 u0, u1;                                                       \
        u0.x = f2tf(fb0.x); u0.y = f2tf(fb0.y);                             \
        u0.z = f2tf(fb0.z); u0.w = f2tf(fb0.w);                             \
        u1.x = f2tf(fb1.x); u1.y = f2tf(fb1.y);                             \
        u1.z = f2tf(fb1.z); u1.w = f2tf(fb1.w);                             \
        *(uint4*)(bb_ + bng * 4) = u0;                                      \
        *(uint4*)(bb_ + (bng + 16) * 4) = u1;                               \
    } while (0)

    #define GEMM_COMPUTE(buf) do {                                         \
        uint4 alo[4], ahi[4];                                               \
        const unsigned* ab_ = sA + (buf) * SA_WORDS;                        \
        _Pragma("unroll")                                                   \
        for (int mt = 0; mt < 4; mt++) {                                    \
            int r_  = wm * 64 + mt * 16 + g;                                \
            int r2_ = r_ + 8;                                               \
            alo[mt] = *(const uint4*)(ab_ + r_  * 16 + ((t ^ ((r_  >> 1) & 3)) << 2)); \
            ahi[mt] = *(const uint4*)(ab_ + r2_ * 16 + ((t ^ ((r2_ >> 1) & 3)) << 2)); \
        }                                                                   \
        unsigned bf[4][4];                                                  \
        const unsigned* bbase_ = sB + (buf) * SB_WORDS;                     \
        _Pragma("unroll")                                                   \
        for (int nt = 0; nt < 4; nt++) {                                    \
            const unsigned* b_ = bbase_ + wn * 32 + nt * 8 + g;             \
            bf[nt][0] = b_[ t       * SB_STRIDE];                           \
            bf[nt][1] = b_[(t + 4)  * SB_STRIDE];                           \
            bf[nt][2] = b_[(t + 8)  * SB_STRIDE];                           \
            bf[nt][3] = b_[(t + 12) * SB_STRIDE];                           \
        }                                                                   \
        _Pragma("unroll")                                                   \
        for (int mt = 0; mt < 4; mt++) {                                    \
            unsigned a0_[4] = {alo[mt].x, ahi[mt].x, alo[mt].y, ahi[mt].y}; \
            unsigned a1_[4] = {alo[mt].z, ahi[mt].z, alo[mt].w, ahi[mt].w}; \
            _Pragma("unroll")                                               \
            for (int nt = 0; nt < 4; nt++) {                                \
                mma8(acc[mt][nt], a0_, &bf[nt][0]);                         \
                mma8(acc[mt][nt], a1_, &bf[nt][2]);                         \
            }                                                               \
        }                                                                   \
    } while (0)

    GEMM_LDG(0);
    GEMM_STS(0);
    __syncthreads();

    for (int it = 0; it < NITER; it++) {
        const int buf = it & 1;
        if (it + 1 < NITER) GEMM_LDG(it + 1);
        GEMM_COMPUTE(buf);
        if (it + 1 < NITER) {
            GEMM_STS(buf ^ 1);
            __syncthreads();
        }
    }

    #undef GEMM_LDG
    #undef GEMM_STS
    #undef GEMM_COMPUTE
}

// ---------------------------------------------------------------------------
// Kernel 1: unified QKV projection. grid = (24 ntiles over 3072, 63 mtiles)
// n_global = which*1024 + h*64 + d;  out[(b*HH+h)*SS+s)*DD+d] = x@w + bias
// ---------------------------------------------------------------------------
__global__ __launch_bounds__(256) void qkv_gemm_kernel(
    const float* __restrict__ x,
    const float* __restrict__ wq, const float* __restrict__ bq,
    const float* __restrict__ wk, const float* __restrict__ bk_,
    const float* __restrict__ wv, const float* __restrict__ bv)
{
    __shared__ unsigned sA[2 * SA_WORDS];
    __shared__ unsigned sB[2 * SB_WORDS];

    const int n0g   = blockIdx.x * TNn;       // 0..2944
    const int which = n0g >> 10;
    const int n0    = n0g & 1023;
    const int m0    = blockIdx.y * TMm;

    const float* ws[3]   = {wq, wk, wv};
    const float* bias3[3] = {bq, bk_, bv};
    float* outs[3]       = {g_q, g_k, g_v};
    const float* bias = bias3[which];
    float* out        = outs[which];

    BLQKV bl; bl.w = ws[which]; bl.n0 = n0;

    float acc[4][4][4] = {};
    gemm_core(x, m0, bl, sA, sB, acc);

    const int tid  = threadIdx.x;
    const int lane = tid & 31, wid = tid >> 5;
    const int g = lane >> 2, t = lane & 3;
    const int wm = wid >> 2, wn = wid & 3;

    #pragma unroll
    for (int nt = 0; nt < 4; nt++) {
        const int nc = n0 + wn * 32 + nt * 8 + 2 * t;   // col within this which
        const int h  = nc >> 6;
        const int d  = nc & 63;
        const float bi0 = bias[h * DD + d];
        const float bi1 = bias[h * DD + d + 1];
        #pragma unroll
        for (int mt = 0; mt < 4; mt++) {
            #pragma unroll
            for (int half = 0; half < 2; half++) {
                const int m = m0 + wm * 64 + mt * 16 + g + half * 8;
                if (m < MM) {
                    const int b = m / SS, s = m % SS;
                    float2 r;
                    r.x = acc[mt][nt][half * 2 + 0] + bi0;
                    r.y = acc[mt][nt][half * 2 + 1] + bi1;
                    *(float2*)&out[((size_t)(b * HH + h) * SS + s) * DD + d] = r;
                }
            }
        }
    }
}

// ---------------------------------------------------------------------------
// Kernel 2: causal flash attention, fp32, scale = 1/sqrt(S). (unchanged)
// ---------------------------------------------------------------------------
__global__ __launch_bounds__(256) void flash_kernel()
{
    extern __shared__ float sm[];
    float* qs = sm;                 // 64 x 65
    float* ks = sm + 64 * 65;       // 64 x 65
    float* vs = sm + 2 * 64 * 65;   // 64 x 65
    float* ps = sm + 3 * 64 * 65;   // 64 x 65

    const int qt = blockIdx.x;
    const int bh = blockIdx.y;
    const int b  = bh >> 4;
    const int h  = bh & 15;

    const float* qb = g_q + (size_t)bh * SS * DD;
    const float* kb = g_k + (size_t)bh * SS * DD;
    const float* vb = g_v + (size_t)bh * SS * DD;

    const int tid = threadIdx.x;
    const int tx = tid & 15, ty = tid >> 4;
    const float scale = 0.031622776601683794f;  // 1/sqrt(1000)
    const float NEG_INF = __int_as_float(0xff800000);

    // load Q tile
    {
        int row = tid >> 4;
        int d4  = (tid & 15) * 4;
        #pragma unroll
        for (int r0 = 0; r0 < 64; r0 += 16) {
            int rr = r0 + row;
            int gs = qt * 64 + rr;
            float4 f = (gs < SS) ? *(const float4*)&qb[gs * DD + d4]
                                 : make_float4(0.f, 0.f, 0.f, 0.f);
            qs[rr * 65 + d4 + 0] = f.x;
            qs[rr * 65 + d4 + 1] = f.y;
            qs[rr * 65 + d4 + 2] = f.z;
            qs[rr * 65 + d4 + 3] = f.w;
        }
    }

    float o[4][4] = {};
    float mrow[4], lrow[4];
    #pragma unroll
    for (int i = 0; i < 4; i++) { mrow[i] = NEG_INF; lrow[i] = 0.f; }

    for (int jt = 0; jt <= qt; jt++) {
        __syncthreads();
        {
            int row = tid >> 4;
            int d4  = (tid & 15) * 4;
            #pragma unroll
            for (int r0 = 0; r0 < 64; r0 += 16) {
                int rr = r0 + row;
                int gs = jt * 64 + rr;
                float4 fk, fv;
                if (gs < SS) {
                    fk = *(const float4*)&kb[gs * DD + d4];
                    fv = *(const float4*)&vb[gs * DD + d4];
                } else {
                    fk = make_float4(0.f, 0.f, 0.f, 0.f);
                    fv = fk;
                }
                ks[rr * 65 + d4 + 0] = fk.x; ks[rr * 65 + d4 + 1] = fk.y;
                ks[rr * 65 + d4 + 2] = fk.z; ks[rr * 65 + d4 + 3] = fk.w;
                vs[rr * 65 + d4 + 0] = fv.x; vs[rr * 65 + d4 + 1] = fv.y;
                vs[rr * 65 + d4 + 2] = fv.z; vs[rr * 65 + d4 + 3] = fv.w;
            }
        }
        __syncthreads();

        float s[4][4] = {};
        #pragma unroll 8
        for (int d = 0; d < 64; d++) {
            float a[4], bq_[4];
            #pragma unroll
            for (int i = 0; i < 4; i++) a[i]   = qs[(ty * 4 + i) * 65 + d];
            #pragma unroll
            for (int j = 0; j < 4; j++) bq_[j] = ks[(tx * 4 + j) * 65 + d];
            #pragma unroll
            for (int i = 0; i < 4; i++)
                #pragma unroll
                for (int j = 0; j < 4; j++)
                    s[i][j] = fmaf(a[i], bq_[j], s[i][j]);
        }

        if (jt == qt) {
            #pragma unroll
            for (int i = 0; i < 4; i++) {
                int grow = qt * 64 + ty * 4 + i;
                #pragma unroll
                for (int j = 0; j < 4; j++) {
                    int gcol = jt * 64 + tx * 4 + j;
                    s[i][j] = (gcol > grow || gcol >= SS) ? NEG_INF : s[i][j] * scale;
                }
            }
        } else {
            #pragma unroll
            for (int i = 0; i < 4; i++)
                #pragma unroll
                for (int j = 0; j < 4; j++)
                    s[i][j] *= scale;
        }

        #pragma unroll
        for (int i = 0; i < 4; i++) {
            float rm = s[i][0];
            #pragma unroll
            for (int j = 1; j < 4; j++) rm = fmaxf(rm, s[i][j]);
            #pragma unroll
            for (int off = 8; off >= 1; off >>= 1)
                rm = fmaxf(rm, __shfl_xor_sync(0xffffffffu, rm, off, 16));
            float mnew = fmaxf(mrow[i], rm);
            float alpha = __expf(mrow[i] - mnew);
            float rs = 0.f;
            #pragma unroll
            for (int j = 0; j < 4; j++) {
                s[i][j] = __expf(s[i][j] - mnew);
                rs += s[i][j];
            }
            #pragma unroll
            for (int off = 8; off >= 1; off >>= 1)
                rs += __shfl_xor_sync(0xffffffffu, rs, off, 16);
            lrow[i] = lrow[i] * alpha + rs;
            mrow[i] = mnew;
            #pragma unroll
            for (int j = 0; j < 4; j++) o[i][j] *= alpha;
            #pragma unroll
            for (int j = 0; j < 4; j++)
                ps[(ty * 4 + i) * 65 + tx * 4 + j] = s[i][j];
        }
        __syncthreads();

        #pragma unroll 8
        for (int kk = 0; kk < 64; kk++) {
            float pv[4], vv[4];
            #pragma unroll
            for (int i = 0; i < 4; i++) pv[i] = ps[(ty * 4 + i) * 65 + kk];
            #pragma unroll
            for (int j = 0; j < 4; j++) vv[j] = vs[kk * 65 + tx * 4 + j];
            #pragma unroll
            for (int i = 0; i < 4; i++)
                #pragma unroll
                for (int j = 0; j < 4; j++)
                    o[i][j] = fmaf(pv[i], vv[j], o[i][j]);
        }
    }

    #pragma unroll
    for (int i = 0; i < 4; i++) {
        int grow = qt * 64 + ty * 4 + i;
        if (grow < SS) {
            float inv = 1.f / lrow[i];
            float4 r;
            r.x = o[i][0] * inv; r.y = o[i][1] * inv;
            r.z = o[i][2] * inv; r.w = o[i][3] * inv;
            *(float4*)&g_y[((size_t)b * SS + grow) * EE + h * DD + tx * 4] = r;
        }
    }
}

// ---------------------------------------------------------------------------
// Kernel 3: out = GELU(y @ wp + bp). grid = (8 ntiles, 63 mtiles)
// ---------------------------------------------------------------------------
__global__ __launch_bounds__(256) void proj_gelu_kernel(
    const float* __restrict__ wp, const float* __restrict__ bp,
    float* __restrict__ out)
{
    __shared__ unsigned sA[2 * SA_WORDS];
    __shared__ unsigned sB[2 * SB_WORDS];

    const int n0 = blockIdx.x * TNn;
    const int m0 = blockIdx.y * TMm;

    BLP bl; bl.wp = wp; bl.n0 = n0;

    float acc[4][4][4] = {};
    gemm_core(g_y, m0, bl, sA, sB, acc);

    const int tid  = threadIdx.x;
    const int lane = tid & 31, wid = tid >> 5;
    const int g = lane >> 2, t = lane & 3;
    const int wm = wid >> 2, wn = wid & 3;

    #pragma unroll
    for (int nt = 0; nt < 4; nt++) {
        const int col = n0 + wn * 32 + nt * 8 + 2 * t;
        const float bi0 = bp[col];
        const float bi1 = bp[col + 1];
        #pragma unroll
        for (int mt = 0; mt < 4; mt++) {
            #pragma unroll
            for (int half = 0; half < 2; half++) {
                const int m = m0 + wm * 64 + mt * 16 + g + half * 8;
                if (m < MM) {
                    float t0 = acc[mt][nt][half * 2 + 0] + bi0;
                    float t1 = acc[mt][nt][half * 2 + 1] + bi1;
                    float2 r;
                    r.x = 0.5f * t0 * (1.0f + erff(t0 * 0.70710678118654752f));
                    r.y = 0.5f * t1 * (1.0f + erff(t1 * 0.70710678118654752f));
                    *(float2*)&out[(size_t)m * EE + col] = r;
                }
            }
        }
    }
}

// ---------------------------------------------------------------------------
extern "C" void kernel_launch(void* const* d_in, const int* in_sizes, int n_in,
                              void* d_out, int out_size)
{
    const float* x  = (const float*)d_in[0];
    const float* wq = (const float*)d_in[1];
    const float* bq = (const float*)d_in[2];
    const float* wk = (const float*)d_in[3];
    const float* bk = (const float*)d_in[4];
    const float* wv = (const float*)d_in[5];
    const float* bv = (const float*)d_in[6];
    const float* wp = (const float*)d_in[7];
    const float* bp = (const float*)d_in[8];
    float* out = (float*)d_out;

    // Unified QKV projection (tensor core TF32, 128x128 tiles)
    dim3 g1(3 * EE / TNn, MT);     // (24, 63)
    qkv_gemm_kernel<<<g1, 256>>>(x, wq, bq, wk, bk, wv, bv);

    // Flash attention (fp32 SIMT)
    const int smem = 4 * 64 * 65 * sizeof(float);  // 66560 B
    cudaFuncSetAttribute(flash_kernel, cudaFuncAttributeMaxDynamicSharedMemorySize, smem);
    dim3 g2(STILES, BB * HH);
    flash_kernel<<<g2, 256, smem>>>();

    // Output projection + GELU (tensor core TF32)
    dim3 g3(EE / TNn, MT);         // (8, 63)
    proj_gelu_kernel<<<g3, 256>>>(wp, bp, out);
}

// round 7
// speedup vs baseline: 2.9455x; 1.9382x over previous
#include <cuda_runtime.h>
#include <math.h>

#define BB 8
#define SS 1000
#define EE 1024
#define HH 16
#define DD 64
#define MM (BB*SS)        // 8000
#define STILES 16

#define TMm 128
#define TNn 128
#define TKk 16
#define NITER (EE/TKk)    // 64
#define MT ((MM + TMm - 1)/TMm)   // 63

// Scratch (allocation-free rule: __device__ globals)
__device__ float g_q[BB*HH*SS*DD];
__device__ float g_k[BB*HH*SS*DD];
__device__ float g_v[BB*HH*SS*DD];
__device__ float g_y[BB*SS*EE];

// ---------------------------------------------------------------------------
// TF32 helpers
// ---------------------------------------------------------------------------
__device__ __forceinline__ unsigned f2tf(float f) {
    unsigned u;
    asm("cvt.rna.tf32.f32 %0, %1;" : "=r"(u) : "f"(f));
    return u;
}

__device__ __forceinline__ void mma8(float* d, const unsigned* a, const unsigned* b) {
    asm volatile(
        "mma.sync.aligned.m16n8k8.row.col.f32.tf32.tf32.f32 "
        "{%0,%1,%2,%3}, {%4,%5,%6,%7}, {%8,%9}, {%0,%1,%2,%3};"
        : "+f"(d[0]), "+f"(d[1]), "+f"(d[2]), "+f"(d[3])
        : "r"(a[0]), "r"(a[1]), "r"(a[2]), "r"(a[3]),
          "r"(b[0]), "r"(b[1]));
}

// ---------------------------------------------------------------------------
// 128x128x16 TF32 GEMM core, 256 threads = 8 warps (2m x 4n), warp tile 64x32.
// sA: word = row*16 + ((c ^ ((row>>1)&3))<<2) + j, content k = 4j + c.
// sB: [k][n] stride 136.
// ---------------------------------------------------------------------------
#define SA_WORDS 2048
#define SB_STRIDE 136
#define SB_WORDS (16*SB_STRIDE)   // 2176

struct BLQKV {
    const float* w;   // [H][E][D]
    int n0;
    __device__ __forceinline__ float4 ld(int k, int nq) const {
        int n = n0 + nq * 4;
        int h = n >> 6;
        int d = n & 63;
        return *(const float4*)&w[((size_t)h * EE + k) * DD + d];
    }
};

struct BLP {
    const float* wp;  // [E, E]
    int n0;
    __device__ __forceinline__ float4 ld(int k, int nq) const {
        return *(const float4*)&wp[(size_t)k * EE + n0 + nq * 4];
    }
};

template<class BL>
__device__ __forceinline__ void gemm_core(
    const float* __restrict__ Ag, int m0, const BL& bl,
    unsigned* sA, unsigned* sB, float acc[4][4][4])
{
    const int tid  = threadIdx.x;
    const int lane = tid & 31, wid = tid >> 5;
    const int g = lane >> 2, t = lane & 3;
    const int wm = wid >> 2, wn = wid & 3;

    // producer A: 256 threads, each owns half a row (8 k-floats)
    const int arow  = tid >> 1;
    const int ah    = tid & 1;
    const int am    = m0 + arow;
    // producer B: thread owns (k = tid>>4, n-quads tid&15 and (tid&15)+16)
    const int bk  = tid >> 4;
    const int bng = tid & 15;

    float fa[8];
    float4 fb0, fb1;
    const float* aptr = Ag + (size_t)am * EE + ah * 8;

    #define GEMM_LDG(it) do {                                               \
        const int k0_ = (it) * TKk;                                         \
        if (am < MM) {                                                      \
            float4 v0 = *(const float4*)&aptr[k0_];                         \
            float4 v1 = *(const float4*)&aptr[k0_ + 4];                     \
            fa[0]=v0.x; fa[1]=v0.y; fa[2]=v0.z; fa[3]=v0.w;                 \
            fa[4]=v1.x; fa[5]=v1.y; fa[6]=v1.z; fa[7]=v1.w;                 \
        } else {                                                            \
            _Pragma("unroll")                                               \
            for (int i = 0; i < 8; i++) fa[i] = 0.f;                       \
        }                                                                   \
        fb0 = bl.ld(k0_ + bk, bng);                                         \
        fb1 = bl.ld(k0_ + bk, bng + 16);                                    \
    } while (0)

    #define GEMM_STS(buf) do {                                              \
        unsigned* base_ = sA + (buf) * SA_WORDS + arow * 16 + 2 * ah;       \
        const int sw_ = (arow >> 1) & 3;                                    \
        _Pragma("unroll")                                                   \
        for (int c = 0; c < 4; c++) {                                       \
            uint2 u;                                                        \
            u.x = f2tf(fa[c]); u.y = f2tf(fa[4 + c]);                       \
            *(uint2*)(base_ + ((c ^ sw_) << 2)) = u;                        \
        }                                                                   \
        unsigned* bb_ = sB + (buf) * SB_WORDS + bk * SB_STRIDE;             \
        uint4 u0, u1;                                                       \
        u0.x = f2tf(fb0.x); u0.y = f2tf(fb0.y);                             \
        u0.z = f2tf(fb0.z); u0.w = f2tf(fb0.w);                             \
        u1.x = f2tf(fb1.x); u1.y = f2tf(fb1.y);                             \
        u1.z = f2tf(fb1.z); u1.w = f2tf(fb1.w);                             \
        *(uint4*)(bb_ + bng * 4) = u0;                                      \
        *(uint4*)(bb_ + (bng + 16) * 4) = u1;                               \
    } while (0)

    #define GEMM_COMPUTE(buf) do {                                         \
        uint4 alo[4], ahi[4];                                               \
        const unsigned* ab_ = sA + (buf) * SA_WORDS;                        \
        _Pragma("unroll")                                                   \
        for (int mt = 0; mt < 4; mt++) {                                    \
            int r_  = wm * 64 + mt * 16 + g;                                \
            int r2_ = r_ + 8;                                               \
            alo[mt] = *(const uint4*)(ab_ + r_  * 16 + ((t ^ ((r_  >> 1) & 3)) << 2)); \
            ahi[mt] = *(const uint4*)(ab_ + r2_ * 16 + ((t ^ ((r2_ >> 1) & 3)) << 2)); \
        }                                                                   \
        unsigned bf[4][4];                                                  \
        const unsigned* bbase_ = sB + (buf) * SB_WORDS;                     \
        _Pragma("unroll")                                                   \
        for (int nt = 0; nt < 4; nt++) {                                    \
            const unsigned* b_ = bbase_ + wn * 32 + nt * 8 + g;             \
            bf[nt][0] = b_[ t       * SB_STRIDE];                           \
            bf[nt][1] = b_[(t + 4)  * SB_STRIDE];                           \
            bf[nt][2] = b_[(t + 8)  * SB_STRIDE];                           \
            bf[nt][3] = b_[(t + 12) * SB_STRIDE];                           \
        }                                                                   \
        _Pragma("unroll")                                                   \
        for (int mt = 0; mt < 4; mt++) {                                    \
            unsigned a0_[4] = {alo[mt].x, ahi[mt].x, alo[mt].y, ahi[mt].y}; \
            unsigned a1_[4] = {alo[mt].z, ahi[mt].z, alo[mt].w, ahi[mt].w}; \
            _Pragma("unroll")                                               \
            for (int nt = 0; nt < 4; nt++) {                                \
                mma8(acc[mt][nt], a0_, &bf[nt][0]);                         \
                mma8(acc[mt][nt], a1_, &bf[nt][2]);                         \
            }                                                               \
        }                                                                   \
    } while (0)

    GEMM_LDG(0);
    GEMM_STS(0);
    __syncthreads();

    for (int it = 0; it < NITER; it++) {
        const int buf = it & 1;
        if (it + 1 < NITER) GEMM_LDG(it + 1);
        GEMM_COMPUTE(buf);
        if (it + 1 < NITER) {
            GEMM_STS(buf ^ 1);
            __syncthreads();
        }
    }

    #undef GEMM_LDG
    #undef GEMM_STS
    #undef GEMM_COMPUTE
}

// ---------------------------------------------------------------------------
// Kernel 1: unified QKV projection. grid = (24 ntiles over 3072, 63 mtiles)
// ---------------------------------------------------------------------------
__global__ __launch_bounds__(256, 2) void qkv_gemm_kernel(
    const float* __restrict__ x,
    const float* __restrict__ wq, const float* __restrict__ bq,
    const float* __restrict__ wk, const float* __restrict__ bk_,
    const float* __restrict__ wv, const float* __restrict__ bv)
{
    __shared__ unsigned sA[2 * SA_WORDS];
    __shared__ unsigned sB[2 * SB_WORDS];

    const int n0g   = blockIdx.x * TNn;
    const int which = n0g >> 10;
    const int n0    = n0g & 1023;
    const int m0    = blockIdx.y * TMm;

    const float* ws[3]    = {wq, wk, wv};
    const float* bias3[3] = {bq, bk_, bv};
    float* outs[3]        = {g_q, g_k, g_v};
    const float* bias = bias3[which];
    float* out        = outs[which];

    BLQKV bl; bl.w = ws[which]; bl.n0 = n0;

    float acc[4][4][4] = {};
    gemm_core(x, m0, bl, sA, sB, acc);

    const int tid  = threadIdx.x;
    const int lane = tid & 31, wid = tid >> 5;
    const int g = lane >> 2, t = lane & 3;
    const int wm = wid >> 2, wn = wid & 3;

    #pragma unroll
    for (int nt = 0; nt < 4; nt++) {
        const int nc = n0 + wn * 32 + nt * 8 + 2 * t;
        const int h  = nc >> 6;
        const int d  = nc & 63;
        const float bi0 = bias[h * DD + d];
        const float bi1 = bias[h * DD + d + 1];
        #pragma unroll
        for (int mt = 0; mt < 4; mt++) {
            #pragma unroll
            for (int half = 0; half < 2; half++) {
                const int m = m0 + wm * 64 + mt * 16 + g + half * 8;
                if (m < MM) {
                    const int b = m / SS, s = m % SS;
                    float2 r;
                    r.x = acc[mt][nt][half * 2 + 0] + bi0;
                    r.y = acc[mt][nt][half * 2 + 1] + bi1;
                    *(float2*)&out[((size_t)(b * HH + h) * SS + s) * DD + d] = r;
                }
            }
        }
    }
}

// ---------------------------------------------------------------------------
// Kernel 2: causal flash attention on tensor cores (tf32), scale = 1/sqrt(S).
// grid = (16 qtiles, 128 bh), 256 threads = 8 warps (4m x 2n), warp = 16x32.
// smem: qsm/psm in A-swizzled layout; ksm stride 68; vsm stride 72.
// ---------------------------------------------------------------------------
__global__ __launch_bounds__(256, 2) void flash_kernel()
{
    extern __shared__ unsigned fsm[];
    unsigned* qsm = fsm;             // 64*64 = 4096 words (A-layout)
    unsigned* ksm = fsm + 4096;      // 64*68 = 4352 ([seq][d])
    unsigned* vsm = fsm + 8448;      // 64*72 = 4608 ([seq][d])
    unsigned* psm = fsm + 13056;     // 4096 (A-layout)
    float* redm   = (float*)(fsm + 17152);   // [2][64]
    float* reds   = (float*)(fsm + 17280);   // [2][64]  (total 17408 words)

    const int qt = blockIdx.x;
    const int bh = blockIdx.y;
    const int b  = bh >> 4;
    const int h  = bh & 15;

    const float* qb = g_q + (size_t)bh * SS * DD;
    const float* kb = g_k + (size_t)bh * SS * DD;
    const float* vb = g_v + (size_t)bh * SS * DD;

    const int tid  = threadIdx.x;
    const int lane = tid & 31, wid = tid >> 5;
    const int g = lane >> 2, t = lane & 3;
    const int wm2 = wid >> 1, wn2 = wid & 1;
    const int r0  = wm2 * 16 + g;
    const int swL = (r0 >> 1) & 3;
    const int swH = ((r0 + 8) >> 1) & 3;

    const float scale = 0.031622776601683794f;  // 1/sqrt(1000)
    const float NEG_INF = __int_as_float(0xff800000);

    // ---- Q fill: thread -> (row = tid>>2, slab = tid&3), 16 floats
    {
        const int row = tid >> 2, slab = tid & 3;
        const int gs = qt * 64 + row;
        float f[16];
        if (gs < SS) {
            const float* p = qb + (size_t)gs * DD + slab * 16;
            #pragma unroll
            for (int q = 0; q < 4; q++) {
                float4 v = *(const float4*)(p + q * 4);
                f[q*4+0]=v.x; f[q*4+1]=v.y; f[q*4+2]=v.z; f[q*4+3]=v.w;
            }
        } else {
            #pragma unroll
            for (int i = 0; i < 16; i++) f[i] = 0.f;
        }
        const int sw = (row >> 1) & 3;
        unsigned* base = qsm + (row * 4 + slab) * 16;
        #pragma unroll
        for (int c = 0; c < 4; c++) {
            uint4 u;
            u.x = f2tf(f[c]);     u.y = f2tf(f[4 + c]);
            u.z = f2tf(f[8 + c]); u.w = f2tf(f[12 + c]);
            *(uint4*)(base + ((c ^ sw) << 2)) = u;
        }
    }

    float oacc[4][4] = {};
    float mrow[2] = {NEG_INF, NEG_INF};
    float lrow[2] = {0.f, 0.f};

    for (int jt = 0; jt <= qt; jt++) {
        __syncthreads();   // protect ksm/vsm/psm/red from previous iter reads
        // ---- K/V fill (4 passes of 256 float4 loads each)
        #pragma unroll
        for (int p = 0; p < 4; p++) {
            const int idx = p * 256 + tid;     // 0..1023
            const int rr  = idx >> 4;
            const int dq  = (idx & 15) * 4;
            const int gs  = jt * 64 + rr;
            float4 fk, fv;
            if (gs < SS) {
                fk = *(const float4*)&kb[(size_t)gs * DD + dq];
                fv = *(const float4*)&vb[(size_t)gs * DD + dq];
            } else {
                fk = make_float4(0.f, 0.f, 0.f, 0.f);
                fv = fk;
            }
            uint4 uk, uv;
            uk.x = f2tf(fk.x); uk.y = f2tf(fk.y); uk.z = f2tf(fk.z); uk.w = f2tf(fk.w);
            uv.x = f2tf(fv.x); uv.y = f2tf(fv.y); uv.z = f2tf(fv.z); uv.w = f2tf(fv.w);
            *(uint4*)(ksm + rr * 68 + dq) = uk;
            *(uint4*)(vsm + rr * 72 + dq) = uv;
        }
        __syncthreads();

        // ---- S = Q @ K^T   (contraction over d = 64, 8 k8-steps)
        float sacc[4][4] = {};
        #pragma unroll
        for (int s = 0; s < 4; s++) {
            uint4 alo = *(const uint4*)(qsm + (r0 * 4 + s) * 16 + ((t ^ swL) << 2));
            uint4 ahi = *(const uint4*)(qsm + ((r0 + 8) * 4 + s) * 16 + ((t ^ swH) << 2));
            unsigned a1[4] = {alo.x, ahi.x, alo.y, ahi.y};
            unsigned a2[4] = {alo.z, ahi.z, alo.w, ahi.w};
            #pragma unroll
            for (int nt = 0; nt < 4; nt++) {
                const int col = wn2 * 32 + nt * 8 + g;
                const unsigned* kp = ksm + col * 68 + s * 16;
                unsigned b1[2] = {kp[t],     kp[t + 4]};
                unsigned b2[2] = {kp[t + 8], kp[t + 12]};
                mma8(sacc[nt], a1, b1);
                mma8(sacc[nt], a2, b2);
            }
        }

        // ---- scale + causal mask (diagonal tile only)
        if (jt == qt) {
            #pragma unroll
            for (int nt = 0; nt < 4; nt++) {
                #pragma unroll
                for (int e = 0; e < 4; e++) {
                    const int grow = qt * 64 + r0 + (e >> 1) * 8;
                    const int gcol = jt * 64 + wn2 * 32 + nt * 8 + 2 * t + (e & 1);
                    sacc[nt][e] = (gcol > grow || gcol >= SS) ? NEG_INF
                                                              : sacc[nt][e] * scale;
                }
            }
        } else {
            #pragma unroll
            for (int nt = 0; nt < 4; nt++)
                #pragma unroll
                for (int e = 0; e < 4; e++)
                    sacc[nt][e] *= scale;
        }

        // ---- row max (warp part), cross-warp via smem
        #pragma unroll
        for (int rr = 0; rr < 2; rr++) {
            float v = fmaxf(fmaxf(sacc[0][rr*2], sacc[0][rr*2+1]),
                            fmaxf(sacc[1][rr*2], sacc[1][rr*2+1]));
            v = fmaxf(v, fmaxf(fmaxf(sacc[2][rr*2], sacc[2][rr*2+1]),
                               fmaxf(sacc[3][rr*2], sacc[3][rr*2+1])));
            v = fmaxf(v, __shfl_xor_sync(0xffffffffu, v, 1));
            v = fmaxf(v, __shfl_xor_sync(0xffffffffu, v, 2));
            if (t == 0) redm[wn2 * 64 + r0 + rr * 8] = v;
        }
        __syncthreads();

        // ---- exp, P -> psm (A-layout), partial sums, rescale O
        float alpha[2];
        #pragma unroll
        for (int rr = 0; rr < 2; rr++) {
            const int rl = r0 + rr * 8;
            const float mtile = fmaxf(redm[rl], redm[64 + rl]);
            const float mnew  = fmaxf(mrow[rr], mtile);
            alpha[rr] = __expf(mrow[rr] - mnew);
            mrow[rr]  = mnew;
            float sum = 0.f;
            const int sw = (rl >> 1) & 3;
            unsigned* pbase = psm + rl * 64;
            #pragma unroll
            for (int nt = 0; nt < 4; nt++) {
                #pragma unroll
                for (int e = 0; e < 2; e++) {
                    const float pv = __expf(sacc[nt][rr * 2 + e] - mnew);
                    sum += pv;
                    const int col  = wn2 * 32 + nt * 8 + 2 * t + e;
                    const int slab = col >> 4, cc = col & 3, j = (col >> 2) & 3;
                    pbase[slab * 16 + ((cc ^ sw) << 2) + j] = f2tf(pv);
                }
                oacc[nt][rr * 2]     *= alpha[rr];
                oacc[nt][rr * 2 + 1] *= alpha[rr];
            }
            sum += __shfl_xor_sync(0xffffffffu, sum, 1);
            sum += __shfl_xor_sync(0xffffffffu, sum, 2);
            if (t == 0) reds[wn2 * 64 + rl] = sum;
        }
        __syncthreads();

        #pragma unroll
        for (int rr = 0; rr < 2; rr++) {
            const int rl = r0 + rr * 8;
            lrow[rr] = lrow[rr] * alpha[rr] + reds[rl] + reds[64 + rl];
        }

        // ---- O += P @ V   (contraction over seq = 64, 8 k8-steps)
        #pragma unroll
        for (int s = 0; s < 4; s++) {
            uint4 alo = *(const uint4*)(psm + (r0 * 4 + s) * 16 + ((t ^ swL) << 2));
            uint4 ahi = *(const uint4*)(psm + ((r0 + 8) * 4 + s) * 16 + ((t ^ swH) << 2));
            unsigned a1[4] = {alo.x, ahi.x, alo.y, ahi.y};
            unsigned a2[4] = {alo.z, ahi.z, alo.w, ahi.w};
            #pragma unroll
            for (int nt = 0; nt < 4; nt++) {
                const int col = wn2 * 32 + nt * 8 + g;
                const unsigned* vp = vsm + (s * 16) * 72 + col;
                unsigned b1[2] = {vp[t * 72],       vp[(t + 4) * 72]};
                unsigned b2[2] = {vp[(t + 8) * 72], vp[(t + 12) * 72]};
                mma8(oacc[nt], a1, b1);
                mma8(oacc[nt], a2, b2);
            }
        }
    }

    // ---- write y[b, s, h*64 + d]
    #pragma unroll
    for (int rr = 0; rr < 2; rr++) {
        const int grow = qt * 64 + r0 + rr * 8;
        if (grow < SS) {
            const float inv = 1.f / lrow[rr];
            #pragma unroll
            for (int nt = 0; nt < 4; nt++) {
                float2 r;
                r.x = oacc[nt][rr * 2]     * inv;
                r.y = oacc[nt][rr * 2 + 1] * inv;
                const int col = wn2 * 32 + nt * 8 + 2 * t;
                *(float2*)&g_y[((size_t)b * SS + grow) * EE + h * DD + col] = r;
            }
        }
    }
}

// ---------------------------------------------------------------------------
// Kernel 3: out = GELU(y @ wp + bp). grid = (8 ntiles, 63 mtiles)
// ---------------------------------------------------------------------------
__global__ __launch_bounds__(256, 2) void proj_gelu_kernel(
    const float* __restrict__ wp, const float* __restrict__ bp,
    float* __restrict__ out)
{
    __shared__ unsigned sA[2 * SA_WORDS];
    __shared__ unsigned sB[2 * SB_WORDS];

    const int n0 = blockIdx.x * TNn;
    const int m0 = blockIdx.y * TMm;

    BLP bl; bl.wp = wp; bl.n0 = n0;

    float acc[4][4][4] = {};
    gemm_core(g_y, m0, bl, sA, sB, acc);

    const int tid  = threadIdx.x;
    const int lane = tid & 31, wid = tid >> 5;
    const int g = lane >> 2, t = lane & 3;
    const int wm = wid >> 2, wn = wid & 3;

    #pragma unroll
    for (int nt = 0; nt < 4; nt++) {
        const int col = n0 + wn * 32 + nt * 8 + 2 * t;
        const float bi0 = bp[col];
        const float bi1 = bp[col + 1];
        #pragma unroll
        for (int mt = 0; mt < 4; mt++) {
            #pragma unroll
            for (int half = 0; half < 2; half++) {
                const int m = m0 + wm * 64 + mt * 16 + g + half * 8;
                if (m < MM) {
                    float t0 = acc[mt][nt][half * 2 + 0] + bi0;
                    float t1 = acc[mt][nt][half * 2 + 1] + bi1;
                    float2 r;
                    r.x = 0.5f * t0 * (1.0f + erff(t0 * 0.70710678118654752f));
                    r.y = 0.5f * t1 * (1.0f + erff(t1 * 0.70710678118654752f));
                    *(float2*)&out[(size_t)m * EE + col] = r;
                }
            }
        }
    }
}

// ---------------------------------------------------------------------------
extern "C" void kernel_launch(void* const* d_in, const int* in_sizes, int n_in,
                              void* d_out, int out_size)
{
    const float* x  = (const float*)d_in[0];
    const float* wq = (const float*)d_in[1];
    const float* bq = (const float*)d_in[2];
    const float* wk = (const float*)d_in[3];
    const float* bk = (const float*)d_in[4];
    const float* wv = (const float*)d_in[5];
    const float* bv = (const float*)d_in[6];
    const float* wp = (const float*)d_in[7];
    const float* bp = (const float*)d_in[8];
    float* out = (float*)d_out;

    // Unified QKV projection (tensor core TF32, 128x128 tiles)
    dim3 g1(3 * EE / TNn, MT);     // (24, 63)
    qkv_gemm_kernel<<<g1, 256>>>(x, wq, bq, wk, bk, wv, bv);

    // Flash attention (tensor core TF32)
    const int fsm_bytes = 17408 * 4;   // 69632 B
    cudaFuncSetAttribute(flash_kernel, cudaFuncAttributeMaxDynamicSharedMemorySize, fsm_bytes);
    dim3 g2(STILES, BB * HH);
    flash_kernel<<<g2, 256, fsm_bytes>>>();

    // Output projection + GELU (tensor core TF32)
    dim3 g3(EE / TNn, MT);         // (8, 63)
    proj_gelu_kernel<<<g3, 256>>>(wp, bp, out);
}

// round 11
// speedup vs baseline: 3.5390x; 1.2015x over previous
#include <cuda_runtime.h>
#include <math.h>

#define BB 8
#define SS 1000
#define EE 1024
#define HH 16
#define DD 64
#define MM (BB*SS)        // 8000
#define STILES 16

#define TMm 128
#define TNn 128
#define TKk 16
#define NITER (EE/TKk)    // 64
#define MT ((MM + TMm - 1)/TMm)   // 63
#define STAGES 4

// Scratch (allocation-free rule: __device__ globals)
__device__ float g_q[BB*HH*SS*DD];
__device__ float g_k[BB*HH*SS*DD];
__device__ float g_v[BB*HH*SS*DD];
__device__ float g_y[BB*SS*EE];
// tf32-prerounded copies (so raw cp.async + HW truncation is lossless)
__device__ float g_x [MM*EE];
__device__ float g_wq[HH*EE*DD];
__device__ float g_wk[HH*EE*DD];
__device__ float g_wv[HH*EE*DD];
__device__ float g_wp[EE*EE];

// ---------------------------------------------------------------------------
// helpers
// ---------------------------------------------------------------------------
__device__ __forceinline__ unsigned f2tf(float f) {
    unsigned u;
    asm("cvt.rna.tf32.f32 %0, %1;" : "=r"(u) : "f"(f));
    return u;
}
__device__ __forceinline__ float f2tf_f(float f) {
    return __uint_as_float(f2tf(f));
}

__device__ __forceinline__ void mma8(float* d, const unsigned* a, const unsigned* b) {
    asm volatile(
        "mma.sync.aligned.m16n8k8.row.col.f32.tf32.tf32.f32 "
        "{%0,%1,%2,%3}, {%4,%5,%6,%7}, {%8,%9}, {%0,%1,%2,%3};"
        : "+f"(d[0]), "+f"(d[1]), "+f"(d[2]), "+f"(d[3])
        : "r"(a[0]), "r"(a[1]), "r"(a[2]), "r"(a[3]),
          "r"(b[0]), "r"(b[1]));
}

// cp.async 16B with src-size predicate (0 -> zero-fill)
__device__ __forceinline__ void cp16z(unsigned saddr, const void* gsrc, int pred16) {
    asm volatile("cp.async.cg.shared.global [%0], [%1], 16, %2;\n"
                 :: "r"(saddr), "l"(gsrc), "r"(pred16));
}
__device__ __forceinline__ void cp_commit() {
    asm volatile("cp.async.commit_group;\n" ::);
}
__device__ __forceinline__ void cp_wait2() {
    asm volatile("cp.async.wait_group 2;\n" ::);
}
__device__ __forceinline__ void cp_wait0() {
    asm volatile("cp.async.wait_group 0;\n" ::);
}

// ---------------------------------------------------------------------------
// Kernel 0: elementwise tf32 pre-round (RNA), float4 grid-stride
// ---------------------------------------------------------------------------
__global__ __launch_bounds__(256) void preround_kernel(
    const float* __restrict__ src, float* __restrict__ dst, int n4)
{
    int i = blockIdx.x * blockDim.x + threadIdx.x;
    int stride = gridDim.x * blockDim.x;
    for (; i < n4; i += stride) {
        float4 v = ((const float4*)src)[i];
        uint4 u;
        u.x = f2tf(v.x); u.y = f2tf(v.y);
        u.z = f2tf(v.z); u.w = f2tf(v.w);
        ((uint4*)dst)[i] = u;
    }
}

// ---------------------------------------------------------------------------
// 128x128x16 TF32 GEMM core, 256 threads = 8 warps (2m x 4n), warp tile 64x32.
// Fully cp.async (A and B), 4 stages. All sources are pre-rounded tf32 bits,
// so the HW truncation inside HMMA.tf32 is exact.
//
// sA (per stage, 2048 words): word = row*16 + (((k>>2) ^ sw(row))<<2) + (k&3),
//   sw(row) = (row>>1)&3. Chunks are k-contiguous 16B -> cp.async-fillable.
// sB (per stage, 16*136 words): [k][n] stride 136.
// ---------------------------------------------------------------------------
#define SA_WORDS 2048
#define SB_STRIDE 136
#define SB_WORDS (16*SB_STRIDE)   // 2176
#define GEMM_SMEM_WORDS (STAGES*(SA_WORDS+SB_WORDS))   // 16896
#define GEMM_SMEM_BYTES (GEMM_SMEM_WORDS*4)            // 67584

struct BLQKV {
    const float* w;   // [H][E][D], pre-rounded
    int n0;
    __device__ __forceinline__ const float* addr(int k, int nq) const {
        int n = n0 + nq * 4;
        int h = n >> 6;
        int d = n & 63;
        return &w[((size_t)h * EE + k) * DD + d];
    }
};

struct BLP {
    const float* wp;  // [E, E], pre-rounded
    int n0;
    __device__ __forceinline__ const float* addr(int k, int nq) const {
        return &wp[(size_t)k * EE + n0 + nq * 4];
    }
};

template<class BL>
__device__ __forceinline__ void gemm_core(
    const float* __restrict__ Ag, int m0, const BL& bl,
    unsigned* sA, unsigned* sB, float acc[4][4][4])
{
    const int tid  = threadIdx.x;
    const int lane = tid & 31, wid = tid >> 5;
    const int g = lane >> 2, t = lane & 3;
    const int wm = wid >> 2, wn = wid & 3;

    // A producer: thread -> (row = tid>>1, half ah = tid&1), 2 x 16B chunks
    const int arow = tid >> 1, ah = tid & 1;
    const int am   = m0 + arow;
    const int swp  = (arow >> 1) & 3;
    const int apred = (am < MM) ? 16 : 0;
    const float* asrc = Ag + (size_t)(am < MM ? am : 0) * EE + ah * 8;

    const unsigned sAu = (unsigned)__cvta_generic_to_shared(sA);
    const unsigned sBu = (unsigned)__cvta_generic_to_shared(sB);
    const unsigned ad0 = (unsigned)(arow * 16 + (((2*ah + 0) ^ swp) << 2)) * 4u;
    const unsigned ad1 = (unsigned)(arow * 16 + (((2*ah + 1) ^ swp) << 2)) * 4u;

    // B producer: thread -> (k = tid>>4, n-quads tid&15 and +16)
    const int bk  = tid >> 4;
    const int bng = tid & 15;
    const unsigned bd0 = (unsigned)(bk * SB_STRIDE + bng * 4) * 4u;
    const unsigned bd1 = (unsigned)(bk * SB_STRIDE + (bng + 16) * 4) * 4u;

    #define ISSUE_AB(it, st) do {                                           \
        const float* s_ = asrc + (it) * TKk;                                \
        const unsigned ab_ = sAu + (unsigned)(st) * (SA_WORDS * 4u);        \
        cp16z(ab_ + ad0, s_, apred);                                        \
        cp16z(ab_ + ad1, s_ + 4, apred);                                    \
        const unsigned bb_ = sBu + (unsigned)(st) * (SB_WORDS * 4u);        \
        cp16z(bb_ + bd0, bl.addr((it) * TKk + bk, bng), 16);                \
        cp16z(bb_ + bd1, bl.addr((it) * TKk + bk, bng + 16), 16);           \
    } while (0)

    #define GEMM_COMPUTE(st) do {                                          \
        const unsigned* ab_ = sA + (st) * SA_WORDS;                         \
        const unsigned* bbase_ = sB + (st) * SB_WORDS;                      \
        unsigned bf[4][4];                                                  \
        _Pragma("unroll")                                                   \
        for (int nt = 0; nt < 4; nt++) {                                    \
            const unsigned* b_ = bbase_ + wn * 32 + nt * 8 + g;             \
            bf[nt][0] = b_[ t       * SB_STRIDE];                           \
            bf[nt][1] = b_[(t + 4)  * SB_STRIDE];                           \
            bf[nt][2] = b_[(t + 8)  * SB_STRIDE];                           \
            bf[nt][3] = b_[(t + 12) * SB_STRIDE];                           \
        }                                                                   \
        const int sws_ = (g >> 1) & 3;                                      \
        _Pragma("unroll")                                                   \
        for (int mt = 0; mt < 4; mt++) {                                    \
            const int r_ = wm * 64 + mt * 16 + g;                           \
            const unsigned* p1 = ab_ + r_ * 16 + t;                         \
            const unsigned* p2 = ab_ + (r_ + 8) * 16 + t;                   \
            unsigned a0_[4] = {p1[((0 ^ sws_) << 2)], p2[((0 ^ sws_) << 2)],\
                               p1[((1 ^ sws_) << 2)], p2[((1 ^ sws_) << 2)]};\
            unsigned a1_[4] = {p1[((2 ^ sws_) << 2)], p2[((2 ^ sws_) << 2)],\
                               p1[((3 ^ sws_) << 2)], p2[((3 ^ sws_) << 2)]};\
            _Pragma("unroll")                                               \
            for (int nt = 0; nt < 4; nt++) {                                \
                mma8(acc[mt][nt], a0_, &bf[nt][0]);                         \
                mma8(acc[mt][nt], a1_, &bf[nt][2]);                         \
            }                                                               \
        }                                                                   \
    } while (0)

    // prologue: 3 stages in flight
    ISSUE_AB(0, 0); cp_commit();
    ISSUE_AB(1, 1); cp_commit();
    ISSUE_AB(2, 2); cp_commit();

    for (int it = 0; it < NITER; it++) {
        const int st = it & (STAGES - 1);
        cp_wait2();
        __syncthreads();             // stage(it) visible to all warps
        GEMM_COMPUTE(st);
        if (it + 3 < NITER) ISSUE_AB(it + 3, (it + 3) & (STAGES - 1));
        cp_commit();                 // possibly-empty group keeps wait count
    }

    #undef ISSUE_AB
    #undef GEMM_COMPUTE
}

// ---------------------------------------------------------------------------
// Kernel 1: unified QKV projection. grid = (24 ntiles over 3072, 63 mtiles)
// Outputs written tf32-prerounded so downstream raw loads are lossless.
// ---------------------------------------------------------------------------
__global__ __launch_bounds__(256, 2) void qkv_gemm_kernel(
    const float* __restrict__ bq, const float* __restrict__ bk_,
    const float* __restrict__ bv)
{
    extern __shared__ unsigned gsm[];
    unsigned* sA = gsm;
    unsigned* sB = gsm + STAGES * SA_WORDS;

    const int n0g   = blockIdx.x * TNn;
    const int which = n0g >> 10;
    const int n0    = n0g & 1023;
    const int m0    = blockIdx.y * TMm;

    const float* ws[3]    = {g_wq, g_wk, g_wv};
    const float* bias3[3] = {bq, bk_, bv};
    float* outs[3]        = {g_q, g_k, g_v};
    const float* bias = bias3[which];
    float* out        = outs[which];

    BLQKV bl; bl.w = ws[which]; bl.n0 = n0;

    float acc[4][4][4] = {};
    gemm_core(g_x, m0, bl, sA, sB, acc);

    const int tid  = threadIdx.x;
    const int lane = tid & 31, wid = tid >> 5;
    const int g = lane >> 2, t = lane & 3;
    const int wm = wid >> 2, wn = wid & 3;

    #pragma unroll
    for (int nt = 0; nt < 4; nt++) {
        const int nc = n0 + wn * 32 + nt * 8 + 2 * t;
        const int h  = nc >> 6;
        const int d  = nc & 63;
        const float bi0 = bias[h * DD + d];
        const float bi1 = bias[h * DD + d + 1];
        #pragma unroll
        for (int mt = 0; mt < 4; mt++) {
            #pragma unroll
            for (int half = 0; half < 2; half++) {
                const int m = m0 + wm * 64 + mt * 16 + g + half * 8;
                if (m < MM) {
                    const int b = m / SS, s = m % SS;
                    float2 r;
                    r.x = f2tf_f(acc[mt][nt][half * 2 + 0] + bi0);
                    r.y = f2tf_f(acc[mt][nt][half * 2 + 1] + bi1);
                    *(float2*)&out[((size_t)(b * HH + h) * SS + s) * DD + d] = r;
                }
            }
        }
    }
}

// ---------------------------------------------------------------------------
// Kernel 2: causal flash attention on tensor cores (tf32), scale = 1/sqrt(S).
// grid = (16 qtiles, 128 bh), 256 threads = 8 warps (4m x 2n), warp = 16x32.
// Q/K/V arrive pre-rounded (raw bits are exact tf32). P staged RNA.
// Output y written tf32-prerounded for the proj kernel's raw loads.
// smem words: qsm 4096 | ksm 2*4352 | vsm 2*4608 | psm 4096 | red 256
// ---------------------------------------------------------------------------
#define F_KSM 4096
#define F_VSM 12800
#define F_PSM 22016
#define F_REDM 26112
#define F_REDS 26240
#define F_WORDS 26368
#define F_BYTES (F_WORDS*4)

__global__ __launch_bounds__(256, 2) void flash_kernel()
{
    extern __shared__ unsigned fsm[];
    unsigned* qsm = fsm;
    unsigned* ksm = fsm + F_KSM;     // 2 bufs, stride 4352 ([seq][d] stride 68)
    unsigned* vsm = fsm + F_VSM;     // 2 bufs, stride 4608 ([seq][d] stride 72)
    unsigned* psm = fsm + F_PSM;
    float* redm   = (float*)(fsm + F_REDM);   // [2][64]
    float* reds   = (float*)(fsm + F_REDS);   // [2][64]

    const int qt = blockIdx.x;
    const int bh = blockIdx.y;
    const int b  = bh >> 4;
    const int h  = bh & 15;

    const float* qb = g_q + (size_t)bh * SS * DD;
    const float* kb = g_k + (size_t)bh * SS * DD;
    const float* vb = g_v + (size_t)bh * SS * DD;

    const int tid  = threadIdx.x;
    const int lane = tid & 31, wid = tid >> 5;
    const int g = lane >> 2, t = lane & 3;
    const int wm2 = wid >> 1, wn2 = wid & 1;
    const int r0  = wm2 * 16 + g;
    const int swL = (r0 >> 1) & 3;
    const int swH = ((r0 + 8) >> 1) & 3;

    const unsigned kbase_u = (unsigned)__cvta_generic_to_shared(ksm);
    const unsigned vbase_u = (unsigned)__cvta_generic_to_shared(vsm);

    const float scale = 0.031622776601683794f;  // 1/sqrt(1000)
    const float NEG_INF = __int_as_float(0xff800000);

    #define ISSUE_KV(j, bf_) do {                                           \
        _Pragma("unroll")                                                   \
        for (int p = 0; p < 4; p++) {                                       \
            const int idx = p * 256 + tid;                                  \
            const int rr  = idx >> 4;                                       \
            const int dq  = (idx & 15) * 4;                                 \
            const int gs  = (j) * 64 + rr;                                  \
            const int pr  = (gs < SS) ? 16 : 0;                             \
            const int gc  = (gs < SS) ? gs : 0;                             \
            cp16z(kbase_u + (unsigned)((bf_) * 4352 + rr * 68 + dq) * 4u,   \
                  kb + (size_t)gc * DD + dq, pr);                           \
            cp16z(vbase_u + (unsigned)((bf_) * 4608 + rr * 72 + dq) * 4u,   \
                  vb + (size_t)gc * DD + dq, pr);                           \
        }                                                                   \
    } while (0)

    // ---- Q fill (raw bits: g_q is pre-rounded tf32)
    {
        const int row = tid >> 2, slab = tid & 3;
        const int gs = qt * 64 + row;
        unsigned f[16];
        if (gs < SS) {
            const float* p = qb + (size_t)gs * DD + slab * 16;
            #pragma unroll
            for (int q = 0; q < 4; q++) {
                uint4 v = *(const uint4*)(p + q * 4);
                f[q*4+0]=v.x; f[q*4+1]=v.y; f[q*4+2]=v.z; f[q*4+3]=v.w;
            }
        } else {
            #pragma unroll
            for (int i = 0; i < 16; i++) f[i] = 0u;
        }
        const int sw = (row >> 1) & 3;
        unsigned* base = qsm + (row * 4 + slab) * 16;
        #pragma unroll
        for (int c = 0; c < 4; c++) {
            uint4 u;
            u.x = f[c];     u.y = f[4 + c];
            u.z = f[8 + c]; u.w = f[12 + c];
            *(uint4*)(base + ((c ^ sw) << 2)) = u;
        }
    }

    // prefetch KV(0)
    ISSUE_KV(0, 0);
    cp_commit();

    float oacc[4][4] = {};
    float mrow[2] = {NEG_INF, NEG_INF};
    float lrow[2] = {0.f, 0.f};

    for (int jt = 0; jt <= qt; jt++) {
        const int buf = jt & 1;
        cp_wait0();
        __syncthreads();   // KV(jt) visible; guards psm/red/Q and buf reuse
        if (jt < qt) { ISSUE_KV(jt + 1, buf ^ 1); cp_commit(); }

        const unsigned* kbuf = ksm + buf * 4352;
        const unsigned* vbuf = vsm + buf * 4608;

        // ---- S = Q @ K^T
        float sacc[4][4] = {};
        #pragma unroll
        for (int s = 0; s < 4; s++) {
            uint4 alo = *(const uint4*)(qsm + (r0 * 4 + s) * 16 + ((t ^ swL) << 2));
            uint4 ahi = *(const uint4*)(qsm + ((r0 + 8) * 4 + s) * 16 + ((t ^ swH) << 2));
            unsigned a1[4] = {alo.x, ahi.x, alo.y, ahi.y};
            unsigned a2[4] = {alo.z, ahi.z, alo.w, ahi.w};
            #pragma unroll
            for (int nt = 0; nt < 4; nt++) {
                const int col = wn2 * 32 + nt * 8 + g;
                const unsigned* kp = kbuf + col * 68 + s * 16;
                unsigned b1[2] = {kp[t],     kp[t + 4]};
                unsigned b2[2] = {kp[t + 8], kp[t + 12]};
                mma8(sacc[nt], a1, b1);
                mma8(sacc[nt], a2, b2);
            }
        }

        // ---- scale + causal mask (diagonal tile only)
        if (jt == qt) {
            #pragma unroll
            for (int nt = 0; nt < 4; nt++) {
                #pragma unroll
                for (int e = 0; e < 4; e++) {
                    const int grow = qt * 64 + r0 + (e >> 1) * 8;
                    const int gcol = jt * 64 + wn2 * 32 + nt * 8 + 2 * t + (e & 1);
                    sacc[nt][e] = (gcol > grow || gcol >= SS) ? NEG_INF
                                                              : sacc[nt][e] * scale;
                }
            }
        } else {
            #pragma unroll
            for (int nt = 0; nt < 4; nt++)
                #pragma unroll
                for (int e = 0; e < 4; e++)
                    sacc[nt][e] *= scale;
        }

        // ---- row max (warp part), cross-warp via smem
        #pragma unroll
        for (int rr = 0; rr < 2; rr++) {
            float v = fmaxf(fmaxf(sacc[0][rr*2], sacc[0][rr*2+1]),
                            fmaxf(sacc[1][rr*2], sacc[1][rr*2+1]));
            v = fmaxf(v, fmaxf(fmaxf(sacc[2][rr*2], sacc[2][rr*2+1]),
                               fmaxf(sacc[3][rr*2], sacc[3][rr*2+1])));
            v = fmaxf(v, __shfl_xor_sync(0xffffffffu, v, 1));
            v = fmaxf(v, __shfl_xor_sync(0xffffffffu, v, 2));
            if (t == 0) redm[wn2 * 64 + r0 + rr * 8] = v;
        }
        __syncthreads();

        // ---- exp, P -> psm (RNA, A-layout), partial sums, rescale O
        float alpha[2];
        #pragma unroll
        for (int rr = 0; rr < 2; rr++) {
            const int rl = r0 + rr * 8;
            const float mtile = fmaxf(redm[rl], redm[64 + rl]);
            const float mnew  = fmaxf(mrow[rr], mtile);
            alpha[rr] = __expf(mrow[rr] - mnew);
            mrow[rr]  = mnew;
            float sum = 0.f;
            const int sw = (rl >> 1) & 3;
            unsigned* pbase = psm + rl * 64;
            #pragma unroll
            for (int nt = 0; nt < 4; nt++) {
                #pragma unroll
                for (int e = 0; e < 2; e++) {
                    const float pv = __expf(sacc[nt][rr * 2 + e] - mnew);
                    sum += pv;
                    const int col  = wn2 * 32 + nt * 8 + 2 * t + e;
                    const int slab = col >> 4, cc = col & 3, j = (col >> 2) & 3;
                    pbase[slab * 16 + ((cc ^ sw) << 2) + j] = f2tf(pv);
                }
                oacc[nt][rr * 2]     *= alpha[rr];
                oacc[nt][rr * 2 + 1] *= alpha[rr];
            }
            sum += __shfl_xor_sync(0xffffffffu, sum, 1);
            sum += __shfl_xor_sync(0xffffffffu, sum, 2);
            if (t == 0) reds[wn2 * 64 + rl] = sum;
        }
        __syncthreads();

        #pragma unroll
        for (int rr = 0; rr < 2; rr++) {
            const int rl = r0 + rr * 8;
            lrow[rr] = lrow[rr] * alpha[rr] + reds[rl] + reds[64 + rl];
        }

        // ---- O += P @ V
        #pragma unroll
        for (int s = 0; s < 4; s++) {
            uint4 alo = *(const uint4*)(psm + (r0 * 4 + s) * 16 + ((t ^ swL) << 2));
            uint4 ahi = *(const uint4*)(psm + ((r0 + 8) * 4 + s) * 16 + ((t ^ swH) << 2));
            unsigned a1[4] = {alo.x, ahi.x, alo.y, ahi.y};
            unsigned a2[4] = {alo.z, ahi.z, alo.w, ahi.w};
            #pragma unroll
            for (int nt = 0; nt < 4; nt++) {
                const int col = wn2 * 32 + nt * 8 + g;
                const unsigned* vp = vbuf + (s * 16) * 72 + col;
                unsigned b1[2] = {vp[t * 72],       vp[(t + 4) * 72]};
                unsigned b2[2] = {vp[(t + 8) * 72], vp[(t + 12) * 72]};
                mma8(oacc[nt], a1, b1);
                mma8(oacc[nt], a2, b2);
            }
        }
    }

    // ---- write y[b, s, h*64 + d], tf32-prerounded for proj's raw loads
    #pragma unroll
    for (int rr = 0; rr < 2; rr++) {
        const int grow = qt * 64 + r0 + rr * 8;
        if (grow < SS) {
            const float inv = 1.f / lrow[rr];
            #pragma unroll
            for (int nt = 0; nt < 4; nt++) {
                float2 r;
                r.x = f2tf_f(oacc[nt][rr * 2]     * inv);
                r.y = f2tf_f(oacc[nt][rr * 2 + 1] * inv);
                const int col = wn2 * 32 + nt * 8 + 2 * t;
                *(float2*)&g_y[((size_t)b * SS + grow) * EE + h * DD + col] = r;
            }
        }
    }
    #undef ISSUE_KV
}

// ---------------------------------------------------------------------------
// Kernel 3: out = GELU(y @ wp + bp). grid = (8 ntiles, 63 mtiles)
// ---------------------------------------------------------------------------
__global__ __launch_bounds__(256, 2) void proj_gelu_kernel(
    const float* __restrict__ bp, float* __restrict__ out)
{
    extern __shared__ unsigned gsm[];
    unsigned* sA = gsm;
    unsigned* sB = gsm + STAGES * SA_WORDS;

    const int n0 = blockIdx.x * TNn;
    const int m0 = blockIdx.y * TMm;

    BLP bl; bl.wp = g_wp; bl.n0 = n0;

    float acc[4][4][4] = {};
    gemm_core(g_y, m0, bl, sA, sB, acc);

    const int tid  = threadIdx.x;
    const int lane = tid & 31, wid = tid >> 5;
    const int g = lane >> 2, t = lane & 3;
    const int wm = wid >> 2, wn = wid & 3;

    #pragma unroll
    for (int nt = 0; nt < 4; nt++) {
        const int col = n0 + wn * 32 + nt * 8 + 2 * t;
        const float bi0 = bp[col];
        const float bi1 = bp[col + 1];
        #pragma unroll
        for (int mt = 0; mt < 4; mt++) {
            #pragma unroll
            for (int half = 0; half < 2; half++) {
                const int m = m0 + wm * 64 + mt * 16 + g + half * 8;
                if (m < MM) {
                    float t0 = acc[mt][nt][half * 2 + 0] + bi0;
                    float t1 = acc[mt][nt][half * 2 + 1] + bi1;
                    float2 r;
                    r.x = 0.5f * t0 * (1.0f + erff(t0 * 0.70710678118654752f));
                    r.y = 0.5f * t1 * (1.0f + erff(t1 * 0.70710678118654752f));
                    *(float2*)&out[(size_t)m * EE + col] = r;
                }
            }
        }
    }
}

// ---------------------------------------------------------------------------
extern "C" void kernel_launch(void* const* d_in, const int* in_sizes, int n_in,
                              void* d_out, int out_size)
{
    const float* x  = (const float*)d_in[0];
    const float* wq = (const float*)d_in[1];
    const float* bq = (const float*)d_in[2];
    const float* wk = (const float*)d_in[3];
    const float* bk = (const float*)d_in[4];
    const float* wv = (const float*)d_in[5];
    const float* bv = (const float*)d_in[6];
    const float* wp = (const float*)d_in[7];
    const float* bp = (const float*)d_in[8];
    float* out = (float*)d_out;

    cudaFuncSetAttribute(qkv_gemm_kernel,
                         cudaFuncAttributeMaxDynamicSharedMemorySize, GEMM_SMEM_BYTES);
    cudaFuncSetAttribute(proj_gelu_kernel,
                         cudaFuncAttributeMaxDynamicSharedMemorySize, GEMM_SMEM_BYTES);
    cudaFuncSetAttribute(flash_kernel,
                         cudaFuncAttributeMaxDynamicSharedMemorySize, F_BYTES);

    // resolve scratch symbol addresses (host-side; graph-capture safe)
    float *p_x, *p_wq, *p_wk, *p_wv, *p_wp;
    cudaGetSymbolAddress((void**)&p_x,  g_x);
    cudaGetSymbolAddress((void**)&p_wq, g_wq);
    cudaGetSymbolAddress((void**)&p_wk, g_wk);
    cudaGetSymbolAddress((void**)&p_wv, g_wv);
    cudaGetSymbolAddress((void**)&p_wp, g_wp);

    // Pre-round inputs/weights to tf32 (RNA) so cp.async raw loads are exact
    preround_kernel<<<4096, 256>>>(x,  p_x,  MM * EE / 4);
    preround_kernel<<<1024, 256>>>(wq, p_wq, HH * EE * DD / 4);
    preround_kernel<<<1024, 256>>>(wk, p_wk, HH * EE * DD / 4);
    preround_kernel<<<1024, 256>>>(wv, p_wv, HH * EE * DD / 4);
    preround_kernel<<<1024, 256>>>(wp, p_wp, EE * EE / 4);

    // Unified QKV projection (tensor core TF32, 4-stage double-sided cp.async)
    dim3 g1(3 * EE / TNn, MT);     // (24, 63)
    qkv_gemm_kernel<<<g1, 256, GEMM_SMEM_BYTES>>>(bq, bk, bv);

    // Flash attention (tensor core TF32, double-buffered cp.async K/V)
    dim3 g2(STILES, BB * HH);
    flash_kernel<<<g2, 256, F_BYTES>>>();

    // Output projection + GELU
    dim3 g3(EE / TNn, MT);         // (8, 63)
    proj_gelu_kernel<<<g3, 256, GEMM_SMEM_BYTES>>>(bp, out);
}

// round 12
// speedup vs baseline: 3.5420x; 1.0008x over previous
#include <cuda_runtime.h>
#include <math.h>

#define BB 8
#define SS 1000
#define EE 1024
#define HH 16
#define DD 64
#define MM (BB*SS)        // 8000
#define STILES 16

#define TMm 128
#define TNn 128
#define TKk 16
#define NITER (EE/TKk)    // 64
#define MT ((MM + TMm - 1)/TMm)   // 63
#define STAGES 4

// Scratch (allocation-free rule: __device__ globals)
__device__ float g_q[BB*HH*SS*DD];
__device__ float g_k[BB*HH*SS*DD];
__device__ float g_v[BB*HH*SS*DD];
__device__ float g_y[BB*SS*EE];
// tf32-prerounded copies (so raw cp.async + HW truncation is lossless)
__device__ float g_x [MM*EE];
__device__ float g_wq[HH*EE*DD];
__device__ float g_wk[HH*EE*DD];
__device__ float g_wv[HH*EE*DD];
__device__ float g_wp[EE*EE];

// ---------------------------------------------------------------------------
// helpers
// ---------------------------------------------------------------------------
__device__ __forceinline__ unsigned f2tf(float f) {
    unsigned u;
    asm("cvt.rna.tf32.f32 %0, %1;" : "=r"(u) : "f"(f));
    return u;
}
__device__ __forceinline__ float f2tf_f(float f) {
    return __uint_as_float(f2tf(f));
}

__device__ __forceinline__ void mma8(float* d, const unsigned* a, const unsigned* b) {
    asm volatile(
        "mma.sync.aligned.m16n8k8.row.col.f32.tf32.tf32.f32 "
        "{%0,%1,%2,%3}, {%4,%5,%6,%7}, {%8,%9}, {%0,%1,%2,%3};"
        : "+f"(d[0]), "+f"(d[1]), "+f"(d[2]), "+f"(d[3])
        : "r"(a[0]), "r"(a[1]), "r"(a[2]), "r"(a[3]),
          "r"(b[0]), "r"(b[1]));
}

// cp.async 16B with src-size predicate (0 -> zero-fill)
__device__ __forceinline__ void cp16z(unsigned saddr, const void* gsrc, int pred16) {
    asm volatile("cp.async.cg.shared.global [%0], [%1], 16, %2;\n"
                 :: "r"(saddr), "l"(gsrc), "r"(pred16));
}
__device__ __forceinline__ void cp_commit() {
    asm volatile("cp.async.commit_group;\n" ::);
}
__device__ __forceinline__ void cp_wait2() {
    asm volatile("cp.async.wait_group 2;\n" ::);
}
__device__ __forceinline__ void cp_wait0() {
    asm volatile("cp.async.wait_group 0;\n" ::);
}

// ---------------------------------------------------------------------------
// Kernel 0: elementwise tf32 pre-round (RNA), float4 grid-stride
// ---------------------------------------------------------------------------
__global__ __launch_bounds__(256) void preround_kernel(
    const float* __restrict__ src, float* __restrict__ dst, int n4)
{
    int i = blockIdx.x * blockDim.x + threadIdx.x;
    int stride = gridDim.x * blockDim.x;
    for (; i < n4; i += stride) {
        float4 v = ((const float4*)src)[i];
        uint4 u;
        u.x = f2tf(v.x); u.y = f2tf(v.y);
        u.z = f2tf(v.z); u.w = f2tf(v.w);
        ((uint4*)dst)[i] = u;
    }
}

// ---------------------------------------------------------------------------
// 128x128x16 TF32 GEMM core, 256 threads = 8 warps (2m x 4n), warp tile 64x32.
// Fully cp.async (A and B), 4 stages. All sources are pre-rounded tf32 bits,
// so the HW truncation inside HMMA.tf32 is exact.
//
// sA (per stage, 2048 words): word = row*16 + (((k>>2) ^ sw(row))<<2) + (k&3),
//   sw(row) = (row>>1)&3. Chunks are k-contiguous 16B -> cp.async-fillable.
// sB (per stage, 16*136 words): [k][n] stride 136.
// ---------------------------------------------------------------------------
#define SA_WORDS 2048
#define SB_STRIDE 136
#define SB_WORDS (16*SB_STRIDE)   // 2176
#define GEMM_SMEM_WORDS (STAGES*(SA_WORDS+SB_WORDS))   // 16896
#define GEMM_SMEM_BYTES (GEMM_SMEM_WORDS*4)            // 67584

struct BLQKV {
    const float* w;   // [H][E][D], pre-rounded
    int n0;
    __device__ __forceinline__ const float* addr(int k, int nq) const {
        int n = n0 + nq * 4;
        int h = n >> 6;
        int d = n & 63;
        return &w[((size_t)h * EE + k) * DD + d];
    }
};

struct BLP {
    const float* wp;  // [E, E], pre-rounded
    int n0;
    __device__ __forceinline__ const float* addr(int k, int nq) const {
        return &wp[(size_t)k * EE + n0 + nq * 4];
    }
};

template<class BL>
__device__ __forceinline__ void gemm_core(
    const float* __restrict__ Ag, int m0, const BL& bl,
    unsigned* sA, unsigned* sB, float acc[4][4][4])
{
    const int tid  = threadIdx.x;
    const int lane = tid & 31, wid = tid >> 5;
    const int g = lane >> 2, t = lane & 3;
    const int wm = wid >> 2, wn = wid & 3;

    // A producer: thread -> (row = tid>>1, half ah = tid&1), 2 x 16B chunks
    const int arow = tid >> 1, ah = tid & 1;
    const int am   = m0 + arow;
    const int swp  = (arow >> 1) & 3;
    const int apred = (am < MM) ? 16 : 0;
    const float* asrc = Ag + (size_t)(am < MM ? am : 0) * EE + ah * 8;

    const unsigned sAu = (unsigned)__cvta_generic_to_shared(sA);
    const unsigned sBu = (unsigned)__cvta_generic_to_shared(sB);
    const unsigned ad0 = (unsigned)(arow * 16 + (((2*ah + 0) ^ swp) << 2)) * 4u;
    const unsigned ad1 = (unsigned)(arow * 16 + (((2*ah + 1) ^ swp) << 2)) * 4u;

    // B producer: thread -> (k = tid>>4, n-quads tid&15 and +16)
    const int bk  = tid >> 4;
    const int bng = tid & 15;
    const unsigned bd0 = (unsigned)(bk * SB_STRIDE + bng * 4) * 4u;
    const unsigned bd1 = (unsigned)(bk * SB_STRIDE + (bng + 16) * 4) * 4u;

    #define ISSUE_AB(it, st) do {                                           \
        const float* s_ = asrc + (it) * TKk;                                \
        const unsigned ab_ = sAu + (unsigned)(st) * (SA_WORDS * 4u);        \
        cp16z(ab_ + ad0, s_, apred);                                        \
        cp16z(ab_ + ad1, s_ + 4, apred);                                    \
        const unsigned bb_ = sBu + (unsigned)(st) * (SB_WORDS * 4u);        \
        cp16z(bb_ + bd0, bl.addr((it) * TKk + bk, bng), 16);                \
        cp16z(bb_ + bd1, bl.addr((it) * TKk + bk, bng + 16), 16);           \
    } while (0)

    #define GEMM_COMPUTE(st) do {                                          \
        const unsigned* ab_ = sA + (st) * SA_WORDS;                         \
        const unsigned* bbase_ = sB + (st) * SB_WORDS;                      \
        unsigned bf[4][4];                                                  \
        _Pragma("unroll")                                                   \
        for (int nt = 0; nt < 4; nt++) {                                    \
            const unsigned* b_ = bbase_ + wn * 32 + nt * 8 + g;             \
            bf[nt][0] = b_[ t       * SB_STRIDE];                           \
            bf[nt][1] = b_[(t + 4)  * SB_STRIDE];                           \
            bf[nt][2] = b_[(t + 8)  * SB_STRIDE];                           \
            bf[nt][3] = b_[(t + 12) * SB_STRIDE];                           \
        }                                                                   \
        const int sws_ = (g >> 1) & 3;                                      \
        _Pragma("unroll")                                                   \
        for (int mt = 0; mt < 4; mt++) {                                    \
            const int r_ = wm * 64 + mt * 16 + g;                           \
            const unsigned* p1 = ab_ + r_ * 16 + t;                         \
            const unsigned* p2 = ab_ + (r_ + 8) * 16 + t;                   \
            unsigned a0_[4] = {p1[((0 ^ sws_) << 2)], p2[((0 ^ sws_) << 2)],\
                               p1[((1 ^ sws_) << 2)], p2[((1 ^ sws_) << 2)]};\
            unsigned a1_[4] = {p1[((2 ^ sws_) << 2)], p2[((2 ^ sws_) << 2)],\
                               p1[((3 ^ sws_) << 2)], p2[((3 ^ sws_) << 2)]};\
            _Pragma("unroll")                                               \
            for (int nt = 0; nt < 4; nt++) {                                \
                mma8(acc[mt][nt], a0_, &bf[nt][0]);                         \
                mma8(acc[mt][nt], a1_, &bf[nt][2]);                         \
            }                                                               \
        }                                                                   \
    } while (0)

    // prologue: 3 stages in flight
    ISSUE_AB(0, 0); cp_commit();
    ISSUE_AB(1, 1); cp_commit();
    ISSUE_AB(2, 2); cp_commit();

    for (int it = 0; it < NITER; it++) {
        const int st = it & (STAGES - 1);
        cp_wait2();
        __syncthreads();             // stage(it) visible to all warps
        GEMM_COMPUTE(st);
        if (it + 3 < NITER) ISSUE_AB(it + 3, (it + 3) & (STAGES - 1));
        cp_commit();                 // possibly-empty group keeps wait count
    }

    #undef ISSUE_AB
    #undef GEMM_COMPUTE
}

// ---------------------------------------------------------------------------
// Kernel 1: unified QKV projection. grid = (24 ntiles over 3072, 63 mtiles)
// Outputs written tf32-prerounded so downstream raw loads are lossless.
// ---------------------------------------------------------------------------
__global__ __launch_bounds__(256, 2) void qkv_gemm_kernel(
    const float* __restrict__ bq, const float* __restrict__ bk_,
    const float* __restrict__ bv)
{
    extern __shared__ unsigned gsm[];
    unsigned* sA = gsm;
    unsigned* sB = gsm + STAGES * SA_WORDS;

    const int n0g   = blockIdx.x * TNn;
    const int which = n0g >> 10;
    const int n0    = n0g & 1023;
    const int m0    = blockIdx.y * TMm;

    const float* ws[3]    = {g_wq, g_wk, g_wv};
    const float* bias3[3] = {bq, bk_, bv};
    float* outs[3]        = {g_q, g_k, g_v};
    const float* bias = bias3[which];
    float* out        = outs[which];

    BLQKV bl; bl.w = ws[which]; bl.n0 = n0;

    float acc[4][4][4] = {};
    gemm_core(g_x, m0, bl, sA, sB, acc);

    const int tid  = threadIdx.x;
    const int lane = tid & 31, wid = tid >> 5;
    const int g = lane >> 2, t = lane & 3;
    const int wm = wid >> 2, wn = wid & 3;

    #pragma unroll
    for (int nt = 0; nt < 4; nt++) {
        const int nc = n0 + wn * 32 + nt * 8 + 2 * t;
        const int h  = nc >> 6;
        const int d  = nc & 63;
        const float bi0 = bias[h * DD + d];
        const float bi1 = bias[h * DD + d + 1];
        #pragma unroll
        for (int mt = 0; mt < 4; mt++) {
            #pragma unroll
            for (int half = 0; half < 2; half++) {
                const int m = m0 + wm * 64 + mt * 16 + g + half * 8;
                if (m < MM) {
                    const int b = m / SS, s = m % SS;
                    float2 r;
                    r.x = f2tf_f(acc[mt][nt][half * 2 + 0] + bi0);
                    r.y = f2tf_f(acc[mt][nt][half * 2 + 1] + bi1);
                    *(float2*)&out[((size_t)(b * HH + h) * SS + s) * DD + d] = r;
                }
            }
        }
    }
}

// ---------------------------------------------------------------------------
// Kernel 2: causal flash attention on tensor cores (tf32), scale = 1/sqrt(S).
// grid = (16 qtiles, 128 bh), 256 threads = 8 warps (4m x 2n), warp = 16x32.
// Q/K/V arrive pre-rounded (raw bits are exact tf32). P staged RNA.
// Output y written tf32-prerounded for the proj kernel's raw loads.
// smem words: qsm 4096 | ksm 2*4352 | vsm 2*4608 | psm 4096 | red 256
// ---------------------------------------------------------------------------
#define F_KSM 4096
#define F_VSM 12800
#define F_PSM 22016
#define F_REDM 26112
#define F_REDS 26240
#define F_WORDS 26368
#define F_BYTES (F_WORDS*4)

__global__ __launch_bounds__(256, 2) void flash_kernel()
{
    extern __shared__ unsigned fsm[];
    unsigned* qsm = fsm;
    unsigned* ksm = fsm + F_KSM;     // 2 bufs, stride 4352 ([seq][d] stride 68)
    unsigned* vsm = fsm + F_VSM;     // 2 bufs, stride 4608 ([seq][d] stride 72)
    unsigned* psm = fsm + F_PSM;
    float* redm   = (float*)(fsm + F_REDM);   // [2][64]
    float* reds   = (float*)(fsm + F_REDS);   // [2][64]

    const int qt = blockIdx.x;
    const int bh = blockIdx.y;
    const int b  = bh >> 4;
    const int h  = bh & 15;

    const float* qb = g_q + (size_t)bh * SS * DD;
    const float* kb = g_k + (size_t)bh * SS * DD;
    const float* vb = g_v + (size_t)bh * SS * DD;

    const int tid  = threadIdx.x;
    const int lane = tid & 31, wid = tid >> 5;
    const int g = lane >> 2, t = lane & 3;
    const int wm2 = wid >> 1, wn2 = wid & 1;
    const int r0  = wm2 * 16 + g;
    const int swL = (r0 >> 1) & 3;
    const int swH = ((r0 + 8) >> 1) & 3;

    const unsigned kbase_u = (unsigned)__cvta_generic_to_shared(ksm);
    const unsigned vbase_u = (unsigned)__cvta_generic_to_shared(vsm);

    const float scale = 0.031622776601683794f;  // 1/sqrt(1000)
    const float NEG_INF = __int_as_float(0xff800000);

    #define ISSUE_KV(j, bf_) do {                                           \
        _Pragma("unroll")                                                   \
        for (int p = 0; p < 4; p++) {                                       \
            const int idx = p * 256 + tid;                                  \
            const int rr  = idx >> 4;                                       \
            const int dq  = (idx & 15) * 4;                                 \
            const int gs  = (j) * 64 + rr;                                  \
            const int pr  = (gs < SS) ? 16 : 0;                             \
            const int gc  = (gs < SS) ? gs : 0;                             \
            cp16z(kbase_u + (unsigned)((bf_) * 4352 + rr * 68 + dq) * 4u,   \
                  kb + (size_t)gc * DD + dq, pr);                           \
            cp16z(vbase_u + (unsigned)((bf_) * 4608 + rr * 72 + dq) * 4u,   \
                  vb + (size_t)gc * DD + dq, pr);                           \
        }                                                                   \
    } while (0)

    // ---- Q fill (raw bits: g_q is pre-rounded tf32)
    {
        const int row = tid >> 2, slab = tid & 3;
        const int gs = qt * 64 + row;
        unsigned f[16];
        if (gs < SS) {
            const float* p = qb + (size_t)gs * DD + slab * 16;
            #pragma unroll
            for (int q = 0; q < 4; q++) {
                uint4 v = *(const uint4*)(p + q * 4);
                f[q*4+0]=v.x; f[q*4+1]=v.y; f[q*4+2]=v.z; f[q*4+3]=v.w;
            }
        } else {
            #pragma unroll
            for (int i = 0; i < 16; i++) f[i] = 0u;
        }
        const int sw = (row >> 1) & 3;
        unsigned* base = qsm + (row * 4 + slab) * 16;
        #pragma unroll
        for (int c = 0; c < 4; c++) {
            uint4 u;
            u.x = f[c];     u.y = f[4 + c];
            u.z = f[8 + c]; u.w = f[12 + c];
            *(uint4*)(base + ((c ^ sw) << 2)) = u;
        }
    }

    // prefetch KV(0)
    ISSUE_KV(0, 0);
    cp_commit();

    float oacc[4][4] = {};
    float mrow[2] = {NEG_INF, NEG_INF};
    float lrow[2] = {0.f, 0.f};

    for (int jt = 0; jt <= qt; jt++) {
        const int buf = jt & 1;
        cp_wait0();
        __syncthreads();   // KV(jt) visible; guards psm/red/Q and buf reuse
        if (jt < qt) { ISSUE_KV(jt + 1, buf ^ 1); cp_commit(); }

        const unsigned* kbuf = ksm + buf * 4352;
        const unsigned* vbuf = vsm + buf * 4608;

        // ---- S = Q @ K^T
        float sacc[4][4] = {};
        #pragma unroll
        for (int s = 0; s < 4; s++) {
            uint4 alo = *(const uint4*)(qsm + (r0 * 4 + s) * 16 + ((t ^ swL) << 2));
            uint4 ahi = *(const uint4*)(qsm + ((r0 + 8) * 4 + s) * 16 + ((t ^ swH) << 2));
            unsigned a1[4] = {alo.x, ahi.x, alo.y, ahi.y};
            unsigned a2[4] = {alo.z, ahi.z, alo.w, ahi.w};
            #pragma unroll
            for (int nt = 0; nt < 4; nt++) {
                const int col = wn2 * 32 + nt * 8 + g;
                const unsigned* kp = kbuf + col * 68 + s * 16;
                unsigned b1[2] = {kp[t],     kp[t + 4]};
                unsigned b2[2] = {kp[t + 8], kp[t + 12]};
                mma8(sacc[nt], a1, b1);
                mma8(sacc[nt], a2, b2);
            }
        }

        // ---- scale + causal mask (diagonal tile only)
        if (jt == qt) {
            #pragma unroll
            for (int nt = 0; nt < 4; nt++) {
                #pragma unroll
                for (int e = 0; e < 4; e++) {
                    const int grow = qt * 64 + r0 + (e >> 1) * 8;
                    const int gcol = jt * 64 + wn2 * 32 + nt * 8 + 2 * t + (e & 1);
                    sacc[nt][e] = (gcol > grow || gcol >= SS) ? NEG_INF
                                                              : sacc[nt][e] * scale;
                }
            }
        } else {
            #pragma unroll
            for (int nt = 0; nt < 4; nt++)
                #pragma unroll
                for (int e = 0; e < 4; e++)
                    sacc[nt][e] *= scale;
        }

        // ---- row max (warp part), cross-warp via smem
        #pragma unroll
        for (int rr = 0; rr < 2; rr++) {
            float v = fmaxf(fmaxf(sacc[0][rr*2], sacc[0][rr*2+1]),
                            fmaxf(sacc[1][rr*2], sacc[1][rr*2+1]));
            v = fmaxf(v, fmaxf(fmaxf(sacc[2][rr*2], sacc[2][rr*2+1]),
                               fmaxf(sacc[3][rr*2], sacc[3][rr*2+1])));
            v = fmaxf(v, __shfl_xor_sync(0xffffffffu, v, 1));
            v = fmaxf(v, __shfl_xor_sync(0xffffffffu, v, 2));
            if (t == 0) redm[wn2 * 64 + r0 + rr * 8] = v;
        }
        __syncthreads();

        // ---- exp, P -> psm (RNA, A-layout), partial sums, rescale O
        float alpha[2];
        #pragma unroll
        for (int rr = 0; rr < 2; rr++) {
            const int rl = r0 + rr * 8;
            const float mtile = fmaxf(redm[rl], redm[64 + rl]);
            const float mnew  = fmaxf(mrow[rr], mtile);
            alpha[rr] = __expf(mrow[rr] - mnew);
            mrow[rr]  = mnew;
            float sum = 0.f;
            const int sw = (rl >> 1) & 3;
            unsigned* pbase = psm + rl * 64;
            #pragma unroll
            for (int nt = 0; nt < 4; nt++) {
                #pragma unroll
                for (int e = 0; e < 2; e++) {
                    const float pv = __expf(sacc[nt][rr * 2 + e] - mnew);
                    sum += pv;
                    const int col  = wn2 * 32 + nt * 8 + 2 * t + e;
                    const int slab = col >> 4, cc = col & 3, j = (col >> 2) & 3;
                    pbase[slab * 16 + ((cc ^ sw) << 2) + j] = f2tf(pv);
                }
                oacc[nt][rr * 2]     *= alpha[rr];
                oacc[nt][rr * 2 + 1] *= alpha[rr];
            }
            sum += __shfl_xor_sync(0xffffffffu, sum, 1);
            sum += __shfl_xor_sync(0xffffffffu, sum, 2);
            if (t == 0) reds[wn2 * 64 + rl] = sum;
        }
        __syncthreads();

        #pragma unroll
        for (int rr = 0; rr < 2; rr++) {
            const int rl = r0 + rr * 8;
            lrow[rr] = lrow[rr] * alpha[rr] + reds[rl] + reds[64 + rl];
        }

        // ---- O += P @ V
        #pragma unroll
        for (int s = 0; s < 4; s++) {
            uint4 alo = *(const uint4*)(psm + (r0 * 4 + s) * 16 + ((t ^ swL) << 2));
            uint4 ahi = *(const uint4*)(psm + ((r0 + 8) * 4 + s) * 16 + ((t ^ swH) << 2));
            unsigned a1[4] = {alo.x, ahi.x, alo.y, ahi.y};
            unsigned a2[4] = {alo.z, ahi.z, alo.w, ahi.w};
            #pragma unroll
            for (int nt = 0; nt < 4; nt++) {
                const int col = wn2 * 32 + nt * 8 + g;
                const unsigned* vp = vbuf + (s * 16) * 72 + col;
                unsigned b1[2] = {vp[t * 72],       vp[(t + 4) * 72]};
                unsigned b2[2] = {vp[(t + 8) * 72], vp[(t + 12) * 72]};
                mma8(oacc[nt], a1, b1);
                mma8(oacc[nt], a2, b2);
            }
        }
    }

    // ---- write y[b, s, h*64 + d], tf32-prerounded for proj's raw loads
    #pragma unroll
    for (int rr = 0; rr < 2; rr++) {
        const int grow = qt * 64 + r0 + rr * 8;
        if (grow < SS) {
            const float inv = 1.f / lrow[rr];
            #pragma unroll
            for (int nt = 0; nt < 4; nt++) {
                float2 r;
                r.x = f2tf_f(oacc[nt][rr * 2]     * inv);
                r.y = f2tf_f(oacc[nt][rr * 2 + 1] * inv);
                const int col = wn2 * 32 + nt * 8 + 2 * t;
                *(float2*)&g_y[((size_t)b * SS + grow) * EE + h * DD + col] = r;
            }
        }
    }
    #undef ISSUE_KV
}

// ---------------------------------------------------------------------------
// Kernel 3: out = GELU(y @ wp + bp). grid = (8 ntiles, 63 mtiles)
// ---------------------------------------------------------------------------
__global__ __launch_bounds__(256, 2) void proj_gelu_kernel(
    const float* __restrict__ bp, float* __restrict__ out)
{
    extern __shared__ unsigned gsm[];
    unsigned* sA = gsm;
    unsigned* sB = gsm + STAGES * SA_WORDS;

    const int n0 = blockIdx.x * TNn;
    const int m0 = blockIdx.y * TMm;

    BLP bl; bl.wp = g_wp; bl.n0 = n0;

    float acc[4][4][4] = {};
    gemm_core(g_y, m0, bl, sA, sB, acc);

    const int tid  = threadIdx.x;
    const int lane = tid & 31, wid = tid >> 5;
    const int g = lane >> 2, t = lane & 3;
    const int wm = wid >> 2, wn = wid & 3;

    #pragma unroll
    for (int nt = 0; nt < 4; nt++) {
        const int col = n0 + wn * 32 + nt * 8 + 2 * t;
        const float bi0 = bp[col];
        const float bi1 = bp[col + 1];
        #pragma unroll
        for (int mt = 0; mt < 4; mt++) {
            #pragma unroll
            for (int half = 0; half < 2; half++) {
                const int m = m0 + wm * 64 + mt * 16 + g + half * 8;
                if (m < MM) {
                    float t0 = acc[mt][nt][half * 2 + 0] + bi0;
                    float t1 = acc[mt][nt][half * 2 + 1] + bi1;
                    float2 r;
                    r.x = 0.5f * t0 * (1.0f + erff(t0 * 0.70710678118654752f));
                    r.y = 0.5f * t1 * (1.0f + erff(t1 * 0.70710678118654752f));
                    *(float2*)&out[(size_t)m * EE + col] = r;
                }
            }
        }
    }
}

// ---------------------------------------------------------------------------
extern "C" void kernel_launch(void* const* d_in, const int* in_sizes, int n_in,
                              void* d_out, int out_size)
{
    const float* x  = (const float*)d_in[0];
    const float* wq = (const float*)d_in[1];
    const float* bq = (const float*)d_in[2];
    const float* wk = (const float*)d_in[3];
    const float* bk = (const float*)d_in[4];
    const float* wv = (const float*)d_in[5];
    const float* bv = (const float*)d_in[6];
    const float* wp = (const float*)d_in[7];
    const float* bp = (const float*)d_in[8];
    float* out = (float*)d_out;

    cudaFuncSetAttribute(qkv_gemm_kernel,
                         cudaFuncAttributeMaxDynamicSharedMemorySize, GEMM_SMEM_BYTES);
    cudaFuncSetAttribute(proj_gelu_kernel,
                         cudaFuncAttributeMaxDynamicSharedMemorySize, GEMM_SMEM_BYTES);
    cudaFuncSetAttribute(flash_kernel,
                         cudaFuncAttributeMaxDynamicSharedMemorySize, F_BYTES);

    // resolve scratch symbol addresses (host-side; graph-capture safe)
    float *p_x, *p_wq, *p_wk, *p_wv, *p_wp;
    cudaGetSymbolAddress((void**)&p_x,  g_x);
    cudaGetSymbolAddress((void**)&p_wq, g_wq);
    cudaGetSymbolAddress((void**)&p_wk, g_wk);
    cudaGetSymbolAddress((void**)&p_wv, g_wv);
    cudaGetSymbolAddress((void**)&p_wp, g_wp);

    // Pre-round inputs/weights to tf32 (RNA) so cp.async raw loads are exact
    preround_kernel<<<4096, 256>>>(x,  p_x,  MM * EE / 4);
    preround_kernel<<<1024, 256>>>(wq, p_wq, HH * EE * DD / 4);
    preround_kernel<<<1024, 256>>>(wk, p_wk, HH * EE * DD / 4);
    preround_kernel<<<1024, 256>>>(wv, p_wv, HH * EE * DD / 4);
    preround_kernel<<<1024, 256>>>(wp, p_wp, EE * EE / 4);

    // Unified QKV projection (tensor core TF32, 4-stage double-sided cp.async)
    dim3 g1(3 * EE / TNn, MT);     // (24, 63)
    qkv_gemm_kernel<<<g1, 256, GEMM_SMEM_BYTES>>>(bq, bk, bv);

    // Flash attention (tensor core TF32, double-buffered cp.async K/V)
    dim3 g2(STILES, BB * HH);
    flash_kernel<<<g2, 256, F_BYTES>>>();

    // Output projection + GELU
    dim3 g3(EE / TNn, MT);         // (8, 63)
    proj_gelu_kernel<<<g3, 256, GEMM_SMEM_BYTES>>>(bp, out);
}